// round 15
// baseline (speedup 1.0000x reference)
#include <cuda_runtime.h>
#include <cuda_bf16.h>
#include <stdint.h>
#include <math.h>

// Problem dims
#define S_DIM 2048
#define E_DIM 2048
#define H_DIM 16
#define KD_DIM 128
#define FF_DIM 8192
#define EPS 1e-5f
#define NTOT (2048L * 2048L)

// ---------------- scratch (device globals; no allocations allowed) ----------
__device__ float    g_sc [(long)H_DIM * S_DIM * S_DIM];
__device__ float    g_y  [(long)S_DIM * E_DIM];
__device__ float    g_h  [(long)S_DIM * E_DIM];
__device__ float    g_pt [4L * S_DIM * E_DIM];
__device__ double   g_part[2048];
__device__ float    g_stats[2];
// paired-bf16 hi/lo operand buffers (uint32 = bf16x2)
__device__ uint32_t g_xhi [(long)S_DIM * E_DIM / 2];
__device__ uint32_t g_xlo [(long)S_DIM * E_DIM / 2];
__device__ uint32_t g_wqhi[(long)H_DIM * E_DIM * KD_DIM / 2];
__device__ uint32_t g_wqlo[(long)H_DIM * E_DIM * KD_DIM / 2];
__device__ uint32_t g_wkhi[(long)H_DIM * E_DIM * KD_DIM / 2];
__device__ uint32_t g_wklo[(long)H_DIM * E_DIM * KD_DIM / 2];
__device__ uint32_t g_wvhi[(long)H_DIM * E_DIM * E_DIM / 2];
__device__ uint32_t g_wvlo[(long)H_DIM * E_DIM * E_DIM / 2];
__device__ uint32_t g_w1hi[(long)E_DIM * FF_DIM / 2];
__device__ uint32_t g_w1lo[(long)E_DIM * FF_DIM / 2];
__device__ uint32_t g_w2hi[(long)FF_DIM * E_DIM / 2];
__device__ uint32_t g_w2lo[(long)FF_DIM * E_DIM / 2];
__device__ uint32_t g_qhi [(long)H_DIM * S_DIM * KD_DIM / 2];
__device__ uint32_t g_qlo [(long)H_DIM * S_DIM * KD_DIM / 2];
__device__ uint32_t g_khi [(long)H_DIM * S_DIM * KD_DIM / 2];
__device__ uint32_t g_klo [(long)H_DIM * S_DIM * KD_DIM / 2];
__device__ uint32_t g_vhi [(long)H_DIM * S_DIM * E_DIM / 2];
__device__ uint32_t g_vlo [(long)H_DIM * S_DIM * E_DIM / 2];
__device__ uint32_t g_athi[(long)H_DIM * S_DIM * S_DIM / 2];
__device__ uint32_t g_atlo[(long)H_DIM * S_DIM * S_DIM / 2];
__device__ uint32_t g_hhi [(long)S_DIM * E_DIM / 2];
__device__ uint32_t g_hlo [(long)S_DIM * E_DIM / 2];
__device__ uint32_t g_ffhi[(long)S_DIM * FF_DIM / 2];
__device__ uint32_t g_fflo[(long)S_DIM * FF_DIM / 2];

// ===================== helpers ==============================================
__device__ __forceinline__ void split_pair(float f0, float f1,
                                           uint32_t &hi, uint32_t &lo)
{
    __nv_bfloat16 h0 = __float2bfloat16_rn(f0);
    __nv_bfloat16 h1 = __float2bfloat16_rn(f1);
    __nv_bfloat16 l0 = __float2bfloat16_rn(f0 - __bfloat162float(h0));
    __nv_bfloat16 l1 = __float2bfloat16_rn(f1 - __bfloat162float(h1));
    unsigned short u0 = __bfloat16_as_ushort(h0);
    unsigned short u1 = __bfloat16_as_ushort(h1);
    unsigned short w0 = __bfloat16_as_ushort(l0);
    unsigned short w1 = __bfloat16_as_ushort(l1);
    hi = (uint32_t)u0 | ((uint32_t)u1 << 16);
    lo = (uint32_t)w0 | ((uint32_t)w1 << 16);
}

__device__ __forceinline__ uint32_t s2u(const void *p)
{
    uint32_t a;
    asm("{ .reg .u64 t; cvta.to.shared.u64 t, %1; cvt.u32.u64 %0, t; }"
        : "=r"(a) : "l"(p));
    return a;
}

__device__ __forceinline__ void cpa16(uint32_t dst, const uint32_t *src)
{
    asm volatile("cp.async.cg.shared.global [%0], [%1], 16;"
                 :: "r"(dst), "l"(src));
}
__device__ __forceinline__ void cp_commit(void)
{
    asm volatile("cp.async.commit_group;");
}
__device__ __forceinline__ void cp_wait1(void)
{
    asm volatile("cp.async.wait_group 1;" ::: "memory");
}
__device__ __forceinline__ void cp_wait0(void)
{
    asm volatile("cp.async.wait_group 0;" ::: "memory");
}

// split fp32 (adjacent pairs) -> hi/lo words (A-type)
__global__ void __launch_bounds__(256) split_rowpair(
    const float *in, uint32_t *hi, uint32_t *lo, long nwords)
{
    long stride = (long)gridDim.x * 256;
    long i;
    for (i = (long)blockIdx.x * 256 + threadIdx.x; i < nwords; i += stride) {
        float a = in[2 * i];
        float b = in[2 * i + 1];
        uint32_t h, l;
        split_pair(a, b, h, l);
        hi[i] = h;
        lo[i] = l;
    }
}

// split fp32 X[batch][K][N] pairing along K -> word[(b)(k/2)(n)] (B-type)
__global__ void __launch_bounds__(256) split_colpair(
    const float *in, uint32_t *hi, uint32_t *lo, int K, int N, long nwords)
{
    long stride = (long)gridDim.x * 256;
    long i;
    long k2n = (long)(K / 2) * N;
    for (i = (long)blockIdx.x * 256 + threadIdx.x; i < nwords; i += stride) {
        long b = i / k2n;
        long rem = i - b * k2n;
        long k2 = rem / N;
        long n = rem - k2 * N;
        const float *base = in + b * (long)K * N;
        float x0 = base[(2 * k2) * (long)N + n];
        float x1 = base[(2 * k2 + 1) * (long)N + n];
        uint32_t h, l;
        split_pair(x0, x1, h, l);
        hi[i] = h;
        lo[i] = l;
    }
}

// ===================== cp.async bf16-pair HMMA engine =======================
// 128 threads, block tile 128x128, warp grid 2x2, warp tile 64x64.
// 3-stage smem ring, one __syncthreads per k16 stage.
// A-tile smem layout: [128 rows][12 words] (8 data + 4 pad) -> (12g+t)%32
// conflict-free fragment reads, 16B-contiguous cp.async staging.
// B-tile smem layout: [8 k2][136 words] (proven conflict-free).
#define STB     24576
#define OFF_AL  6144
#define OFF_BH  12288
#define OFF_BL  18432
#define DSMEM_T 73728

__device__ __forceinline__ void mma16816(float *c, const uint32_t *a,
                                         const uint32_t *b)
{
    asm volatile(
        "mma.sync.aligned.m16n8k16.row.col.f32.bf16.bf16.f32 "
        "{%0,%1,%2,%3},{%4,%5,%6,%7},{%8,%9},{%0,%1,%2,%3};\n"
        : "+f"(c[0]), "+f"(c[1]), "+f"(c[2]), "+f"(c[3])
        : "r"(a[0]), "r"(a[1]), "r"(a[2]), "r"(a[3]), "r"(b[0]), "r"(b[1]));
}

// one k16 step, 64x64 warp tile, B in BTile [8][136]
__device__ __forceinline__ void compute64_bt(
    const uint32_t *AH, const uint32_t *AL,
    const uint32_t *BH, const uint32_t *BL,
    float acc[4][8][4], int m0w, int n0w, int g, int t)
{
    uint32_t bh[8][2];
    uint32_t bl[8][2];
    int na, ma;
    #pragma unroll
    for (na = 0; na < 8; na++) {
        int c = n0w + na * 8 + g;
        bh[na][0] = BH[t * 136 + c];
        bh[na][1] = BH[(t + 4) * 136 + c];
        bl[na][0] = BL[t * 136 + c];
        bl[na][1] = BL[(t + 4) * 136 + c];
    }
    #pragma unroll
    for (ma = 0; ma < 4; ma++) {
        int r0 = m0w + ma * 16 + g;
        uint32_t ah[4];
        uint32_t al[4];
        ah[0] = AH[r0 * 12 + t];
        ah[1] = AH[(r0 + 8) * 12 + t];
        ah[2] = AH[r0 * 12 + t + 4];
        ah[3] = AH[(r0 + 8) * 12 + t + 4];
        al[0] = AL[r0 * 12 + t];
        al[1] = AL[(r0 + 8) * 12 + t];
        al[2] = AL[r0 * 12 + t + 4];
        al[3] = AL[(r0 + 8) * 12 + t + 4];
        #pragma unroll
        for (na = 0; na < 8; na++) {
            mma16816(acc[ma][na], ah, bh[na]);
            mma16816(acc[ma][na], ah, bl[na]);
            mma16816(acc[ma][na], al, bh[na]);
        }
    }
}

// one k16 step, 64x64 warp tile, B in ATile [128][12] (for QK^T)
__device__ __forceinline__ void compute64_at(
    const uint32_t *AH, const uint32_t *AL,
    const uint32_t *BH, const uint32_t *BL,
    float acc[4][8][4], int m0w, int n0w, int g, int t)
{
    uint32_t bh[8][2];
    uint32_t bl[8][2];
    int na, ma;
    #pragma unroll
    for (na = 0; na < 8; na++) {
        int c = n0w + na * 8 + g;
        bh[na][0] = BH[c * 12 + t];
        bh[na][1] = BH[c * 12 + t + 4];
        bl[na][0] = BL[c * 12 + t];
        bl[na][1] = BL[c * 12 + t + 4];
    }
    #pragma unroll
    for (ma = 0; ma < 4; ma++) {
        int r0 = m0w + ma * 16 + g;
        uint32_t ah[4];
        uint32_t al[4];
        ah[0] = AH[r0 * 12 + t];
        ah[1] = AH[(r0 + 8) * 12 + t];
        ah[2] = AH[r0 * 12 + t + 4];
        ah[3] = AH[(r0 + 8) * 12 + t + 4];
        al[0] = AL[r0 * 12 + t];
        al[1] = AL[(r0 + 8) * 12 + t];
        al[2] = AL[r0 * 12 + t + 4];
        al[3] = AL[(r0 + 8) * 12 + t + 4];
        #pragma unroll
        for (na = 0; na < 8; na++) {
            mma16816(acc[ma][na], ah, bh[na]);
            mma16816(acc[ma][na], ah, bl[na]);
            mma16816(acc[ma][na], al, bh[na]);
        }
    }
}

// ---------------- C = A @ B from pre-split operands (cp.async ring) ---------
// A: A-type words [M][K/2] (+z*sA2). B: B-type words [K/2][N] (+z*sB2).
// cmode: 0 = none, 1 = A-type split out (Chi/Clo), 2 = B-type split out.
__global__ void __launch_bounds__(128) bf_gemm(
    const uint32_t *Ahi, const uint32_t *Alo,
    const uint32_t *Bhi, const uint32_t *Blo,
    const float *bias, const float *resid,
    float *Cf, uint32_t *Chi, uint32_t *Clo, int cmode,
    int K, int N,
    long sA2, long sB2, long sBias, long sCf, long sC2, int relu)
{
    extern __shared__ char dsm[];
    uint32_t sb = s2u(dsm);

    long zo = (long)blockIdx.z;
    const float *bi = (bias != 0) ? (bias + zo * sBias) : (const float *)0;

    int tid = threadIdx.x;
    int lane = tid & 31;
    int warp = tid >> 5;
    int g = lane >> 2;
    int t = lane & 3;
    int m0w = (warp >> 1) * 64;
    int n0w = (warp & 1) * 64;
    long row0 = (long)blockIdx.y * 128;
    long col0 = (long)blockIdx.x * 128;

    int K2 = K / 2;
    int bk2 = tid >> 4;
    int bnc = (tid & 15) * 8;

    const uint32_t *AHg = Ahi + zo * sA2 + (row0 + tid) * (long)K2;
    const uint32_t *ALg = Alo + zo * sA2 + (row0 + tid) * (long)K2;
    const uint32_t *BHg = Bhi + zo * sB2 + (long)bk2 * N + col0 + bnc;
    const uint32_t *BLg = Blo + zo * sB2 + (long)bk2 * N + col0 + bnc;

    uint32_t adst = sb + (uint32_t)tid * 48;
    uint32_t bdst = sb + (uint32_t)(bk2 * 136 + bnc) * 4;

    float acc[4][8][4];
    int i0, i1, i2;
    #pragma unroll
    for (i0 = 0; i0 < 4; i0++)
        #pragma unroll
        for (i1 = 0; i1 < 8; i1++)
            #pragma unroll
            for (i2 = 0; i2 < 4; i2++)
                acc[i0][i1][i2] = 0.0f;

    int nst = K / 16;
    int s;
    // prologue: stage 0 and 1
    for (s = 0; s < 2 && s < nst; s++) {
        uint32_t base = (uint32_t)(s % 3) * STB;
        long ka = (long)s * 8;
        long kb = (long)s * 8 * N;
        cpa16(adst + base, AHg + ka);
        cpa16(adst + base + 16, AHg + ka + 4);
        cpa16(adst + base + OFF_AL, ALg + ka);
        cpa16(adst + base + OFF_AL + 16, ALg + ka + 4);
        cpa16(bdst + base + OFF_BH, BHg + kb);
        cpa16(bdst + base + OFF_BH + 16, BHg + kb + 4);
        cpa16(bdst + base + OFF_BL, BLg + kb);
        cpa16(bdst + base + OFF_BL + 16, BLg + kb + 4);
        cp_commit();
    }
    for (s = 0; s < nst; s++) {
        if (s + 1 < nst) cp_wait1(); else cp_wait0();
        __syncthreads();
        if (s + 2 < nst) {
            uint32_t base = (uint32_t)((s + 2) % 3) * STB;
            long ka = (long)(s + 2) * 8;
            long kb = (long)(s + 2) * 8 * N;
            cpa16(adst + base, AHg + ka);
            cpa16(adst + base + 16, AHg + ka + 4);
            cpa16(adst + base + OFF_AL, ALg + ka);
            cpa16(adst + base + OFF_AL + 16, ALg + ka + 4);
            cpa16(bdst + base + OFF_BH, BHg + kb);
            cpa16(bdst + base + OFF_BH + 16, BHg + kb + 4);
            cpa16(bdst + base + OFF_BL, BLg + kb);
            cpa16(bdst + base + OFF_BL + 16, BLg + kb + 4);
            cp_commit();
        }
        {
            const char *p = dsm + (s % 3) * STB;
            compute64_bt((const uint32_t *)p,
                         (const uint32_t *)(p + OFF_AL),
                         (const uint32_t *)(p + OFF_BH),
                         (const uint32_t *)(p + OFF_BL),
                         acc, m0w, n0w, g, t);
        }
    }

    float *cf = (Cf != 0) ? (Cf + zo * sCf) : (float *)0;
    uint32_t *chi = (Chi != 0) ? (Chi + zo * sC2) : (uint32_t *)0;
    uint32_t *clo = (Clo != 0) ? (Clo + zo * sC2) : (uint32_t *)0;
    int N2 = N / 2;

    int ma, na;
    #pragma unroll
    for (ma = 0; ma < 4; ma++) {
        long r = row0 + m0w + ma * 16 + g;
        #pragma unroll
        for (na = 0; na < 8; na++) {
            long c = col0 + n0w + na * 8 + 2 * t;
            float b0 = 0.0f;
            float b1 = 0.0f;
            if (bi != 0) {
                b0 = bi[c];
                b1 = bi[c + 1];
            }
            float v0 = acc[ma][na][0] + b0;
            float v1 = acc[ma][na][1] + b1;
            float w0 = acc[ma][na][2] + b0;
            float w1 = acc[ma][na][3] + b1;
            if (resid != 0) {
                v0 += resid[r * N + c];
                v1 += resid[r * N + c + 1];
                w0 += resid[(r + 8) * N + c];
                w1 += resid[(r + 8) * N + c + 1];
            }
            if (relu != 0) {
                v0 = fmaxf(v0, 0.0f);
                v1 = fmaxf(v1, 0.0f);
                w0 = fmaxf(w0, 0.0f);
                w1 = fmaxf(w1, 0.0f);
            }
            if (cf != 0) {
                cf[r * N + c]           = v0;
                cf[r * N + c + 1]       = v1;
                cf[(r + 8) * N + c]     = w0;
                cf[(r + 8) * N + c + 1] = w1;
            }
            if (cmode == 1) {
                uint32_t h0, l0, h1, l1;
                split_pair(v0, v1, h0, l0);
                split_pair(w0, w1, h1, l1);
                chi[r * N2 + c / 2]       = h0;
                clo[r * N2 + c / 2]       = l0;
                chi[(r + 8) * N2 + c / 2] = h1;
                clo[(r + 8) * N2 + c / 2] = l1;
            } else if (cmode == 2) {
                // B-type: pair rows (r, r+1) via partner lane (g^1 <=> lane^4)
                float ov0 = __shfl_xor_sync(0xffffffffu, v0, 4);
                float ov1 = __shfl_xor_sync(0xffffffffu, v1, 4);
                float ow0 = __shfl_xor_sync(0xffffffffu, w0, 4);
                float ow1 = __shfl_xor_sync(0xffffffffu, w1, 4);
                if ((g & 1) == 0) {
                    uint32_t h0, l0, h1, l1, h2, l2, h3, l3;
                    split_pair(v0, ov0, h0, l0);
                    split_pair(v1, ov1, h1, l1);
                    split_pair(w0, ow0, h2, l2);
                    split_pair(w1, ow1, h3, l3);
                    long p0 = (r >> 1) * (long)N + c;
                    long p1 = ((r + 8) >> 1) * (long)N + c;
                    chi[p0]     = h0;
                    chi[p0 + 1] = h1;
                    clo[p0]     = l0;
                    clo[p0 + 1] = l1;
                    chi[p1]     = h2;
                    chi[p1 + 1] = h3;
                    clo[p1]     = l2;
                    clo[p1 + 1] = l3;
                }
            }
        }
    }
}

// ---------------- scores = (Q @ K^T)/sqrt(KD), causal block skip ------------
__global__ void __launch_bounds__(128) bf_qkt(
    const uint32_t *Qhi, const uint32_t *Qlo,
    const uint32_t *Khi, const uint32_t *Klo,
    float *SCg, float scale)
{
    extern __shared__ char dsm[];

    if (blockIdx.x > blockIdx.y) return;
    uint32_t sb = s2u(dsm);

    long zo = (long)blockIdx.z * S_DIM * (KD_DIM / 2);
    float *C = SCg + (long)blockIdx.z * S_DIM * (long)S_DIM;

    int tid = threadIdx.x;
    int lane = tid & 31;
    int warp = tid >> 5;
    int g = lane >> 2;
    int t = lane & 3;
    int m0w = (warp >> 1) * 64;
    int n0w = (warp & 1) * 64;
    long row0 = (long)blockIdx.y * 128;
    long col0 = (long)blockIdx.x * 128;

    int K2 = KD_DIM / 2;
    const uint32_t *QHg = Qhi + zo + (row0 + tid) * (long)K2;
    const uint32_t *QLg = Qlo + zo + (row0 + tid) * (long)K2;
    const uint32_t *KHg = Khi + zo + (col0 + tid) * (long)K2;
    const uint32_t *KLg = Klo + zo + (col0 + tid) * (long)K2;

    uint32_t adst = sb + (uint32_t)tid * 48;

    float acc[4][8][4];
    int i0, i1, i2;
    #pragma unroll
    for (i0 = 0; i0 < 4; i0++)
        #pragma unroll
        for (i1 = 0; i1 < 8; i1++)
            #pragma unroll
            for (i2 = 0; i2 < 4; i2++)
                acc[i0][i1][i2] = 0.0f;

    int nst = KD_DIM / 16;  // 8
    int s;
    for (s = 0; s < 2 && s < nst; s++) {
        uint32_t base = (uint32_t)(s % 3) * STB;
        long ka = (long)s * 8;
        cpa16(adst + base, QHg + ka);
        cpa16(adst + base + 16, QHg + ka + 4);
        cpa16(adst + base + OFF_AL, QLg + ka);
        cpa16(adst + base + OFF_AL + 16, QLg + ka + 4);
        cpa16(adst + base + OFF_BH, KHg + ka);
        cpa16(adst + base + OFF_BH + 16, KHg + ka + 4);
        cpa16(adst + base + OFF_BL, KLg + ka);
        cpa16(adst + base + OFF_BL + 16, KLg + ka + 4);
        cp_commit();
    }
    for (s = 0; s < nst; s++) {
        if (s + 1 < nst) cp_wait1(); else cp_wait0();
        __syncthreads();
        if (s + 2 < nst) {
            uint32_t base = (uint32_t)((s + 2) % 3) * STB;
            long ka = (long)(s + 2) * 8;
            cpa16(adst + base, QHg + ka);
            cpa16(adst + base + 16, QHg + ka + 4);
            cpa16(adst + base + OFF_AL, QLg + ka);
            cpa16(adst + base + OFF_AL + 16, QLg + ka + 4);
            cpa16(adst + base + OFF_BH, KHg + ka);
            cpa16(adst + base + OFF_BH + 16, KHg + ka + 4);
            cpa16(adst + base + OFF_BL, KLg + ka);
            cpa16(adst + base + OFF_BL + 16, KLg + ka + 4);
            cp_commit();
        }
        {
            const char *p = dsm + (s % 3) * STB;
            compute64_at((const uint32_t *)p,
                         (const uint32_t *)(p + OFF_AL),
                         (const uint32_t *)(p + OFF_BH),
                         (const uint32_t *)(p + OFF_BL),
                         acc, m0w, n0w, g, t);
        }
    }

    int ma, na;
    #pragma unroll
    for (ma = 0; ma < 4; ma++) {
        long r = row0 + m0w + ma * 16 + g;
        #pragma unroll
        for (na = 0; na < 8; na++) {
            long c = col0 + n0w + na * 8 + 2 * t;
            C[r * S_DIM + c]           = acc[ma][na][0] * scale;
            C[r * S_DIM + c + 1]       = acc[ma][na][1] * scale;
            C[(r + 8) * S_DIM + c]     = acc[ma][na][2] * scale;
            C[(r + 8) * S_DIM + c + 1] = acc[ma][na][3] * scale;
        }
    }
}

// ---------------- partial[z] = sum_{h in group z} attn[h] @ V[h] ------------
__global__ void __launch_bounds__(128) bf_attn_av(
    const uint32_t *Athi, const uint32_t *Atlo,
    const uint32_t *Vhi, const uint32_t *Vlo,
    float *Pg)
{
    extern __shared__ char dsm[];
    uint32_t sb = s2u(dsm);

    int tid = threadIdx.x;
    int lane = tid & 31;
    int warp = tid >> 5;
    int g = lane >> 2;
    int t = lane & 3;
    int m0w = (warp >> 1) * 64;
    int n0w = (warp & 1) * 64;
    long row0 = (long)blockIdx.y * 128;
    long col0 = (long)blockIdx.x * 128;

    int bk2 = tid >> 4;
    int bnc = (tid & 15) * 8;

    int nk = ((int)blockIdx.y + 1) * 8;
    int total = 4 * nk;
    int h0 = (int)blockIdx.z * 4;
    long S2 = S_DIM / 2;

    uint32_t adst = sb + (uint32_t)tid * 48;
    uint32_t bdst = sb + (uint32_t)(bk2 * 136 + bnc) * 4;

    float acc[4][8][4];
    int i0, i1, i2;
    #pragma unroll
    for (i0 = 0; i0 < 4; i0++)
        #pragma unroll
        for (i1 = 0; i1 < 8; i1++)
            #pragma unroll
            for (i2 = 0; i2 < 4; i2++)
                acc[i0][i1][i2] = 0.0f;

    int s;
    for (s = 0; s < 2 && s < total; s++) {
        uint32_t base = (uint32_t)(s % 3) * STB;
        int hh = h0 + s / nk;
        int kk = s % nk;
        long ab = ((long)hh * S_DIM + row0 + tid) * S2 + (long)kk * 8;
        long bb = ((long)hh * S2 + (long)kk * 8 + bk2) * E_DIM + col0 + bnc;
        cpa16(adst + base, Athi + ab);
        cpa16(adst + base + 16, Athi + ab + 4);
        cpa16(adst + base + OFF_AL, Atlo + ab);
        cpa16(adst + base + OFF_AL + 16, Atlo + ab + 4);
        cpa16(bdst + base + OFF_BH, Vhi + bb);
        cpa16(bdst + base + OFF_BH + 16, Vhi + bb + 4);
        cpa16(bdst + base + OFF_BL, Vlo + bb);
        cpa16(bdst + base + OFF_BL + 16, Vlo + bb + 4);
        cp_commit();
    }
    for (s = 0; s < total; s++) {
        if (s + 1 < total) cp_wait1(); else cp_wait0();
        __syncthreads();
        if (s + 2 < total) {
            uint32_t base = (uint32_t)((s + 2) % 3) * STB;
            int hh = h0 + (s + 2) / nk;
            int kk = (s + 2) % nk;
            long ab = ((long)hh * S_DIM + row0 + tid) * S2 + (long)kk * 8;
            long bb = ((long)hh * S2 + (long)kk * 8 + bk2) * E_DIM + col0 + bnc;
            cpa16(adst + base, Athi + ab);
            cpa16(adst + base + 16, Athi + ab + 4);
            cpa16(adst + base + OFF_AL, Atlo + ab);
            cpa16(adst + base + OFF_AL + 16, Atlo + ab + 4);
            cpa16(bdst + base + OFF_BH, Vhi + bb);
            cpa16(bdst + base + OFF_BH + 16, Vhi + bb + 4);
            cpa16(bdst + base + OFF_BL, Vlo + bb);
            cpa16(bdst + base + OFF_BL + 16, Vlo + bb + 4);
            cp_commit();
        }
        {
            const char *p = dsm + (s % 3) * STB;
            compute64_bt((const uint32_t *)p,
                         (const uint32_t *)(p + OFF_AL),
                         (const uint32_t *)(p + OFF_BH),
                         (const uint32_t *)(p + OFF_BL),
                         acc, m0w, n0w, g, t);
        }
    }

    float *P = Pg + (long)blockIdx.z * S_DIM * E_DIM;
    int ma, na;
    #pragma unroll
    for (ma = 0; ma < 4; ma++) {
        long r = row0 + m0w + ma * 16 + g;
        #pragma unroll
        for (na = 0; na < 8; na++) {
            long c = col0 + n0w + na * 8 + 2 * t;
            P[r * E_DIM + c]           = acc[ma][na][0];
            P[r * E_DIM + c + 1]       = acc[ma][na][1];
            P[(r + 8) * E_DIM + c]     = acc[ma][na][2];
            P[(r + 8) * E_DIM + c + 1] = acc[ma][na][3];
        }
    }
}

// py = x + p0 + p1 + p2 + p3 (fixed order, deterministic)
__global__ void __launch_bounds__(256) reduce4(
    const float *x, const float *p, float *py)
{
    long stride = (long)gridDim.x * 256;
    long i;
    for (i = (long)blockIdx.x * 256 + threadIdx.x; i < NTOT; i += stride) {
        float v = x[i];
        v += p[i];
        v += p[NTOT + i];
        v += p[2 * NTOT + i];
        v += p[3 * NTOT + i];
        py[i] = v;
    }
}

// ---------------- causal row softmax -> split attn (hi/lo pairs) ------------
__global__ void __launch_bounds__(256) softmax_causal(
    const float *sc, uint32_t *athi, uint32_t *atlo)
{
    __shared__ float buf[S_DIM];
    __shared__ float red[256];

    int s = blockIdx.x;
    int h = blockIdx.y;
    const float *row = sc + ((long)h * S_DIM + s) * (long)S_DIM;
    long out2 = ((long)h * S_DIM + s) * (long)(S_DIM / 2);
    int tid = threadIdx.x;
    int len = s + 1;
    int i;
    int st;

    float lmax = -INFINITY;
    for (i = tid; i < len; i += 256) {
        float v = row[i];
        buf[i] = v;
        lmax = fmaxf(lmax, v);
    }
    red[tid] = lmax;
    __syncthreads();
    for (st = 128; st > 0; st >>= 1) {
        if (tid < st) red[tid] = fmaxf(red[tid], red[tid + st]);
        __syncthreads();
    }
    float m = red[0];
    __syncthreads();

    float lsum = 0.0f;
    for (i = tid; i < len; i += 256) {
        float e = __expf(buf[i] - m);
        buf[i] = e;
        lsum += e;
    }
    red[tid] = lsum;
    __syncthreads();
    for (st = 128; st > 0; st >>= 1) {
        if (tid < st) red[tid] = red[tid] + red[tid + st];
        __syncthreads();
    }
    float inv = 1.0f / red[0];
    for (i = tid; i < S_DIM / 2; i += 256) {
        int i0 = 2 * i;
        int i1 = 2 * i + 1;
        float a = (i0 < len) ? buf[i0] * inv : 0.0f;
        float b = (i1 < len) ? buf[i1] * inv : 0.0f;
        uint32_t hh, ll;
        split_pair(a, b, hh, ll);
        athi[out2 + i] = hh;
        atlo[out2 + i] = ll;
    }
}

// ---------------- global LayerNorm ------------------------------------------
__global__ void __launch_bounds__(256) ln_reduce(const float *y, double *part)
{
    __shared__ double sd[256];
    __shared__ double sq[256];

    double s = 0.0;
    double ss = 0.0;
    long stride = (long)gridDim.x * 256;
    long i;
    int st;
    for (i = (long)blockIdx.x * 256 + threadIdx.x; i < NTOT; i += stride) {
        double v = (double)y[i];
        s += v;
        ss += v * v;
    }
    sd[threadIdx.x] = s;
    sq[threadIdx.x] = ss;
    __syncthreads();
    for (st = 128; st > 0; st >>= 1) {
        if (threadIdx.x < st) {
            sd[threadIdx.x] = sd[threadIdx.x] + sd[threadIdx.x + st];
            sq[threadIdx.x] = sq[threadIdx.x] + sq[threadIdx.x + st];
        }
        __syncthreads();
    }
    if (threadIdx.x == 0) {
        part[blockIdx.x] = sd[0];
        part[1024 + blockIdx.x] = sq[0];
    }
}

__global__ void __launch_bounds__(256) ln_finalize(const double *part, float *stats)
{
    __shared__ double sd[256];
    __shared__ double sq[256];

    double s = 0.0;
    double ss = 0.0;
    int i;
    int st;
    for (i = threadIdx.x; i < 1024; i += 256) {
        s += part[i];
        ss += part[1024 + i];
    }
    sd[threadIdx.x] = s;
    sq[threadIdx.x] = ss;
    __syncthreads();
    for (st = 128; st > 0; st >>= 1) {
        if (threadIdx.x < st) {
            sd[threadIdx.x] = sd[threadIdx.x] + sd[threadIdx.x + st];
            sq[threadIdx.x] = sq[threadIdx.x] + sq[threadIdx.x + st];
        }
        __syncthreads();
    }
    if (threadIdx.x == 0) {
        double mean = sd[0] / (double)NTOT;
        double var = sq[0] / (double)NTOT - mean * mean;
        stats[0] = (float)mean;
        stats[1] = (float)(1.0 / sqrt(var + (double)EPS));
    }
}

__global__ void __launch_bounds__(256) ln_apply(
    const float *y, const float *g, const float *b,
    const float *st, float *of32, uint32_t *ohi, uint32_t *olo)
{
    float m = st[0];
    float is = st[1];
    long stride = (long)gridDim.x * 256;
    long i;
    for (i = (long)blockIdx.x * 256 + threadIdx.x; i < NTOT / 2; i += stride) {
        long i0 = 2 * i;
        long i1 = 2 * i + 1;
        float v0 = (y[i0] - m) * is * g[i0] + b[i0];
        float v1 = (y[i1] - m) * is * g[i1] + b[i1];
        if (of32 != 0) {
            of32[i0] = v0;
            of32[i1] = v1;
        }
        if (ohi != 0) {
            uint32_t hh, ll;
            split_pair(v0, v1, hh, ll);
            ohi[i] = hh;
            olo[i] = ll;
        }
    }
}

// ---------------- host orchestration ----------------------------------------
extern "C" void kernel_launch(void* const* d_in, const int* in_sizes, int n_in,
                              void* d_out, int out_size)
{
    const float *x  = (const float *)d_in[0];
    const float *Wq = (const float *)d_in[1];
    const float *bq = (const float *)d_in[2];
    const float *Wk = (const float *)d_in[3];
    const float *bk = (const float *)d_in[4];
    const float *Wv = (const float *)d_in[5];
    const float *bv = (const float *)d_in[6];
    const float *lg = (const float *)d_in[7];
    const float *lb = (const float *)d_in[8];
    const float *W1 = (const float *)d_in[9];
    const float *b1 = (const float *)d_in[10];
    const float *W2 = (const float *)d_in[11];
    const float *b2 = (const float *)d_in[12];
    float *out = (float *)d_out;

    void *pv_[32];
    cudaGetSymbolAddress(&pv_[0],  g_sc);
    cudaGetSymbolAddress(&pv_[1],  g_y);
    cudaGetSymbolAddress(&pv_[2],  g_h);
    cudaGetSymbolAddress(&pv_[3],  g_pt);
    cudaGetSymbolAddress(&pv_[4],  g_part);
    cudaGetSymbolAddress(&pv_[5],  g_stats);
    cudaGetSymbolAddress(&pv_[6],  g_xhi);
    cudaGetSymbolAddress(&pv_[7],  g_xlo);
    cudaGetSymbolAddress(&pv_[8],  g_wqhi);
    cudaGetSymbolAddress(&pv_[9],  g_wqlo);
    cudaGetSymbolAddress(&pv_[10], g_wkhi);
    cudaGetSymbolAddress(&pv_[11], g_wklo);
    cudaGetSymbolAddress(&pv_[12], g_wvhi);
    cudaGetSymbolAddress(&pv_[13], g_wvlo);
    cudaGetSymbolAddress(&pv_[14], g_w1hi);
    cudaGetSymbolAddress(&pv_[15], g_w1lo);
    cudaGetSymbolAddress(&pv_[16], g_w2hi);
    cudaGetSymbolAddress(&pv_[17], g_w2lo);
    cudaGetSymbolAddress(&pv_[18], g_qhi);
    cudaGetSymbolAddress(&pv_[19], g_qlo);
    cudaGetSymbolAddress(&pv_[20], g_khi);
    cudaGetSymbolAddress(&pv_[21], g_klo);
    cudaGetSymbolAddress(&pv_[22], g_vhi);
    cudaGetSymbolAddress(&pv_[23], g_vlo);
    cudaGetSymbolAddress(&pv_[24], g_athi);
    cudaGetSymbolAddress(&pv_[25], g_atlo);
    cudaGetSymbolAddress(&pv_[26], g_hhi);
    cudaGetSymbolAddress(&pv_[27], g_hlo);
    cudaGetSymbolAddress(&pv_[28], g_ffhi);
    cudaGetSymbolAddress(&pv_[29], g_fflo);

    float *psc    = (float *)pv_[0];
    float *py     = (float *)pv_[1];
    float *ph     = (float *)pv_[2];
    float *ppt    = (float *)pv_[3];
    double *ppart = (double *)pv_[4];
    float *pstats = (float *)pv_[5];
    uint32_t *xhi = (uint32_t *)pv_[6],  *xlo = (uint32_t *)pv_[7];
    uint32_t *wqh = (uint32_t *)pv_[8],  *wql = (uint32_t *)pv_[9];
    uint32_t *wkh = (uint32_t *)pv_[10], *wkl = (uint32_t *)pv_[11];
    uint32_t *wvh = (uint32_t *)pv_[12], *wvl = (uint32_t *)pv_[13];
    uint32_t *w1h = (uint32_t *)pv_[14], *w1l = (uint32_t *)pv_[15];
    uint32_t *w2h = (uint32_t *)pv_[16], *w2l = (uint32_t *)pv_[17];
    uint32_t *qh  = (uint32_t *)pv_[18], *ql  = (uint32_t *)pv_[19];
    uint32_t *kh  = (uint32_t *)pv_[20], *kl  = (uint32_t *)pv_[21];
    uint32_t *vh  = (uint32_t *)pv_[22], *vl  = (uint32_t *)pv_[23];
    uint32_t *ath = (uint32_t *)pv_[24], *atl = (uint32_t *)pv_[25];
    uint32_t *hh  = (uint32_t *)pv_[26], *hl  = (uint32_t *)pv_[27];
    uint32_t *ffh = (uint32_t *)pv_[28], *ffl = (uint32_t *)pv_[29];

    cudaFuncSetAttribute(bf_gemm,
                         cudaFuncAttributeMaxDynamicSharedMemorySize, DSMEM_T);
    cudaFuncSetAttribute(bf_qkt,
                         cudaFuncAttributeMaxDynamicSharedMemorySize, DSMEM_T);
    cudaFuncSetAttribute(bf_attn_av,
                         cudaFuncAttributeMaxDynamicSharedMemorySize, DSMEM_T);

    dim3 blk(256, 1, 1);
    dim3 blkm(128, 1, 1);
    float scale = 1.0f / sqrtf((float)KD_DIM);

    // -------- operand splits --------
    split_rowpair<<<2048, blk>>>(x, xhi, xlo, NTOT / 2);
    split_colpair<<<2048, blk>>>(Wq, wqh, wql, E_DIM, KD_DIM,
                                 (long)H_DIM * E_DIM * KD_DIM / 2);
    split_colpair<<<2048, blk>>>(Wk, wkh, wkl, E_DIM, KD_DIM,
                                 (long)H_DIM * E_DIM * KD_DIM / 2);
    split_colpair<<<4096, blk>>>(Wv, wvh, wvl, E_DIM, E_DIM,
                                 (long)H_DIM * E_DIM * E_DIM / 2);
    split_colpair<<<2048, blk>>>(W1, w1h, w1l, E_DIM, FF_DIM,
                                 (long)E_DIM * FF_DIM / 2);
    split_colpair<<<2048, blk>>>(W2, w2h, w2l, FF_DIM, E_DIM,
                                 (long)FF_DIM * E_DIM / 2);

    // -------- Q/K projections (A-split outputs) --------
    {
        dim3 gq(1, S_DIM / 128, H_DIM);
        bf_gemm<<<gq, blkm, DSMEM_T>>>(xhi, xlo, wqh, wql, bq,
            (const float *)0, (float *)0, qh, ql, 1, E_DIM, KD_DIM,
            0L, (long)(E_DIM / 2) * KD_DIM, (long)KD_DIM,
            0L, (long)S_DIM * (KD_DIM / 2), 0);
        bf_gemm<<<gq, blkm, DSMEM_T>>>(xhi, xlo, wkh, wkl, bk,
            (const float *)0, (float *)0, kh, kl, 1, E_DIM, KD_DIM,
            0L, (long)(E_DIM / 2) * KD_DIM, (long)KD_DIM,
            0L, (long)S_DIM * (KD_DIM / 2), 0);
    }
    // -------- V projection: direct B-type split output --------
    {
        dim3 gv(E_DIM / 128, S_DIM / 128, H_DIM);
        bf_gemm<<<gv, blkm, DSMEM_T>>>(xhi, xlo, wvh, wvl, bv,
            (const float *)0, (float *)0, vh, vl, 2, E_DIM, E_DIM,
            0L, (long)(E_DIM / 2) * E_DIM, (long)E_DIM,
            0L, (long)(S_DIM / 2) * E_DIM, 0);
    }

    // -------- scores + causal softmax (fused attn split) --------
    {
        dim3 gs(S_DIM / 128, S_DIM / 128, H_DIM);
        bf_qkt<<<gs, blkm, DSMEM_T>>>(qh, ql, kh, kl, psc, scale);
    }
    {
        dim3 gsm(S_DIM, H_DIM, 1);
        softmax_causal<<<gsm, blk>>>(psc, ath, atl);
    }

    // -------- attn @ V: 4 balanced head-groups + deterministic reduce -------
    {
        dim3 ga(E_DIM / 128, S_DIM / 128, 4);
        bf_attn_av<<<ga, blkm, DSMEM_T>>>(ath, atl, vh, vl, ppt);
        reduce4<<<2048, blk>>>(x, ppt, py);
    }

    // -------- LN1 --------
    ln_reduce<<<1024, blk>>>(py, ppart);
    ln_finalize<<<1, blk>>>(ppart, pstats);
    ln_apply<<<2048, blk>>>(py, lg, lb, pstats, ph, hh, hl);

    // -------- FFN --------
    {
        dim3 g1(FF_DIM / 128, S_DIM / 128, 1);
        bf_gemm<<<g1, blkm, DSMEM_T>>>(hh, hl, w1h, w1l, b1,
            (const float *)0, (float *)0, ffh, ffl, 1, E_DIM, FF_DIM,
            0L, 0L, 0L, 0L, 0L, 1);
        dim3 g2(E_DIM / 128, S_DIM / 128, 1);
        bf_gemm<<<g2, blkm, DSMEM_T>>>(ffh, ffl, w2h, w2l, b2, ph,
            py, (uint32_t *)0, (uint32_t *)0, 0, FF_DIM, E_DIM,
            0L, 0L, 0L, (long)S_DIM * E_DIM, 0L, 0);
    }

    // -------- LN2 -> output --------
    ln_reduce<<<1024, blk>>>(py, ppart);
    ln_finalize<<<1, blk>>>(ppart, pstats);
    ln_apply<<<2048, blk>>>(py, lg, lb, pstats, out, (uint32_t *)0,
                            (uint32_t *)0);
}

// round 16
// speedup vs baseline: 1.2300x; 1.2300x over previous
#include <cuda_runtime.h>
#include <cuda_bf16.h>
#include <stdint.h>
#include <math.h>

// Problem dims
#define S_DIM 2048
#define E_DIM 2048
#define H_DIM 16
#define KD_DIM 128
#define FF_DIM 8192
#define EPS 1e-5f
#define NTOT (2048L * 2048L)

// ---------------- scratch (device globals; no allocations allowed) ----------
__device__ float    g_sc [(long)H_DIM * S_DIM * S_DIM];
__device__ float    g_y  [(long)S_DIM * E_DIM];
__device__ float    g_h  [(long)S_DIM * E_DIM];
__device__ float    g_pt [4L * S_DIM * E_DIM];
__device__ double   g_part[2048];
__device__ float    g_stats[2];
// paired-bf16 hi/lo operand buffers (uint32 = bf16x2)
__device__ uint32_t g_xhi [(long)S_DIM * E_DIM / 2];
__device__ uint32_t g_xlo [(long)S_DIM * E_DIM / 2];
__device__ uint32_t g_wqhi[(long)H_DIM * E_DIM * KD_DIM / 2];
__device__ uint32_t g_wqlo[(long)H_DIM * E_DIM * KD_DIM / 2];
__device__ uint32_t g_wkhi[(long)H_DIM * E_DIM * KD_DIM / 2];
__device__ uint32_t g_wklo[(long)H_DIM * E_DIM * KD_DIM / 2];
__device__ uint32_t g_wvhi[(long)H_DIM * E_DIM * E_DIM / 2];
__device__ uint32_t g_wvlo[(long)H_DIM * E_DIM * E_DIM / 2];
__device__ uint32_t g_w1hi[(long)E_DIM * FF_DIM / 2];
__device__ uint32_t g_w1lo[(long)E_DIM * FF_DIM / 2];
__device__ uint32_t g_w2hi[(long)FF_DIM * E_DIM / 2];
__device__ uint32_t g_w2lo[(long)FF_DIM * E_DIM / 2];
__device__ uint32_t g_qhi [(long)H_DIM * S_DIM * KD_DIM / 2];
__device__ uint32_t g_qlo [(long)H_DIM * S_DIM * KD_DIM / 2];
__device__ uint32_t g_khi [(long)H_DIM * S_DIM * KD_DIM / 2];
__device__ uint32_t g_klo [(long)H_DIM * S_DIM * KD_DIM / 2];
__device__ uint32_t g_vhi [(long)H_DIM * S_DIM * E_DIM / 2];
__device__ uint32_t g_vlo [(long)H_DIM * S_DIM * E_DIM / 2];
__device__ uint32_t g_athi[(long)H_DIM * S_DIM * S_DIM / 2];
__device__ uint32_t g_atlo[(long)H_DIM * S_DIM * S_DIM / 2];
__device__ uint32_t g_hhi [(long)S_DIM * E_DIM / 2];
__device__ uint32_t g_hlo [(long)S_DIM * E_DIM / 2];
__device__ uint32_t g_ffhi[(long)S_DIM * FF_DIM / 2];
__device__ uint32_t g_fflo[(long)S_DIM * FF_DIM / 2];

// ===================== helpers ==============================================
__device__ __forceinline__ void split_pair(float f0, float f1,
                                           uint32_t &hi, uint32_t &lo)
{
    __nv_bfloat16 h0 = __float2bfloat16_rn(f0);
    __nv_bfloat16 h1 = __float2bfloat16_rn(f1);
    __nv_bfloat16 l0 = __float2bfloat16_rn(f0 - __bfloat162float(h0));
    __nv_bfloat16 l1 = __float2bfloat16_rn(f1 - __bfloat162float(h1));
    unsigned short u0 = __bfloat16_as_ushort(h0);
    unsigned short u1 = __bfloat16_as_ushort(h1);
    unsigned short w0 = __bfloat16_as_ushort(l0);
    unsigned short w1 = __bfloat16_as_ushort(l1);
    hi = (uint32_t)u0 | ((uint32_t)u1 << 16);
    lo = (uint32_t)w0 | ((uint32_t)w1 << 16);
}

// split fp32 (adjacent pairs) -> hi/lo words (A-type)
__global__ void __launch_bounds__(256) split_rowpair(
    const float *in, uint32_t *hi, uint32_t *lo, long nwords)
{
    long stride = (long)gridDim.x * 256;
    long i;
    for (i = (long)blockIdx.x * 256 + threadIdx.x; i < nwords; i += stride) {
        float a = in[2 * i];
        float b = in[2 * i + 1];
        uint32_t h, l;
        split_pair(a, b, h, l);
        hi[i] = h;
        lo[i] = l;
    }
}

// split fp32 X[batch][K][N] pairing along K -> word[(b)(k/2)(n)] (B-type).
// 3-D grid: z=batch, y=k2, x=n-block. No division, fully coalesced.
__global__ void __launch_bounds__(256) split_colpair3d(
    const float *in, uint32_t *hi, uint32_t *lo, int K, int N)
{
    int n = (int)blockIdx.x * 256 + (int)threadIdx.x;
    if (n >= N) return;
    long k2 = (long)blockIdx.y;
    long b = (long)blockIdx.z;
    const float *base = in + b * (long)K * N;
    float x0 = base[(2 * k2) * (long)N + n];
    float x1 = base[(2 * k2 + 1) * (long)N + n];
    uint32_t h, l;
    split_pair(x0, x1, h, l);
    long o = b * (long)(K / 2) * N + k2 * N + n;
    hi[o] = h;
    lo[o] = l;
}

// ===================== bf16-pair SIMT HMMA engine ===========================
#define PITCH 136

struct SmemTiles {
    uint32_t AsH[8][PITCH];
    uint32_t AsL[8][PITCH];
    uint32_t BsH[8][PITCH];
    uint32_t BsL[8][PITCH];
};

__device__ __forceinline__ void mma16816(float *c, const uint32_t *a,
                                         const uint32_t *b)
{
    asm volatile(
        "mma.sync.aligned.m16n8k16.row.col.f32.bf16.bf16.f32 "
        "{%0,%1,%2,%3},{%4,%5,%6,%7},{%8,%9},{%0,%1,%2,%3};\n"
        : "+f"(c[0]), "+f"(c[1]), "+f"(c[2]), "+f"(c[3])
        : "r"(a[0]), "r"(a[1]), "r"(a[2]), "r"(a[3]), "r"(b[0]), "r"(b[1]));
}

__device__ __forceinline__ void compute_stage(const SmemTiles *sm,
    float acc[4][4][4], int m0w, int n0w, int g, int t)
{
    uint32_t bh[4][2];
    uint32_t bl[4][2];
    int na, ma;
    #pragma unroll
    for (na = 0; na < 4; na++) {
        int c = n0w + na * 8 + g;
        bh[na][0] = sm->BsH[t][c];
        bh[na][1] = sm->BsH[t + 4][c];
        bl[na][0] = sm->BsL[t][c];
        bl[na][1] = sm->BsL[t + 4][c];
    }
    #pragma unroll
    for (ma = 0; ma < 4; ma++) {
        int r0 = m0w + ma * 16 + g;
        uint32_t ah[4];
        uint32_t al[4];
        ah[0] = sm->AsH[t][r0];
        ah[1] = sm->AsH[t][r0 + 8];
        ah[2] = sm->AsH[t + 4][r0];
        ah[3] = sm->AsH[t + 4][r0 + 8];
        al[0] = sm->AsL[t][r0];
        al[1] = sm->AsL[t][r0 + 8];
        al[2] = sm->AsL[t + 4][r0];
        al[3] = sm->AsL[t + 4][r0 + 8];
        #pragma unroll
        for (na = 0; na < 4; na++) {
            mma16816(acc[ma][na], ah, bh[na]);
            mma16816(acc[ma][na], ah, bl[na]);
            mma16816(acc[ma][na], al, bh[na]);
        }
    }
}

__device__ __forceinline__ void put_colstage(uint32_t (*Hi)[PITCH],
    uint32_t (*Lo)[PITCH], uint4 h4, uint4 l4, int k2b, int row)
{
    Hi[k2b + 0][row] = h4.x;
    Hi[k2b + 1][row] = h4.y;
    Hi[k2b + 2][row] = h4.z;
    Hi[k2b + 3][row] = h4.w;
    Lo[k2b + 0][row] = l4.x;
    Lo[k2b + 1][row] = l4.y;
    Lo[k2b + 2][row] = l4.z;
    Lo[k2b + 3][row] = l4.w;
}

__device__ __forceinline__ void put_rowstage(SmemTiles *sm,
    uint4 h4, uint4 l4, int k2, int nc)
{
    sm->BsH[k2][nc + 0] = h4.x;
    sm->BsH[k2][nc + 1] = h4.y;
    sm->BsH[k2][nc + 2] = h4.z;
    sm->BsH[k2][nc + 3] = h4.w;
    sm->BsL[k2][nc + 0] = l4.x;
    sm->BsL[k2][nc + 1] = l4.y;
    sm->BsL[k2][nc + 2] = l4.z;
    sm->BsL[k2][nc + 3] = l4.w;
}

// ---------------- C = A @ B from pre-split operands -------------------------
// A: A-type words [M][K/2] (+z*sA2). B: B-type words [K/2][N] (+z*sB2).
// cmode: 0 = none, 1 = A-type split out (Chi/Clo), 2 = B-type split out.
__global__ void __launch_bounds__(256) bf_gemm(
    const uint32_t *Ahi, const uint32_t *Alo,
    const uint32_t *Bhi, const uint32_t *Blo,
    const float *bias, const float *resid,
    float *Cf, uint32_t *Chi, uint32_t *Clo, int cmode,
    int K, int N,
    long sA2, long sB2, long sBias, long sCf, long sC2, int relu)
{
    __shared__ SmemTiles sm[2];

    long zo = (long)blockIdx.z;
    const uint32_t *AH = Ahi + zo * sA2;
    const uint32_t *AL = Alo + zo * sA2;
    const uint32_t *BH = Bhi + zo * sB2;
    const uint32_t *BL = Blo + zo * sB2;
    const float *bi = (bias != 0) ? (bias + zo * sBias) : (const float *)0;

    int tid = threadIdx.x;
    int lane = tid & 31;
    int warp = tid >> 5;
    int g = lane >> 2;
    int t = lane & 3;
    int m0w = (warp >> 2) * 64;
    int n0w = (warp & 3) * 32;
    long row0 = (long)blockIdx.y * 128;
    long col0 = (long)blockIdx.x * 128;

    int arow = tid >> 1;
    int aw4 = (tid & 1) * 4;
    int bkr = tid >> 5;
    int bnc = (tid & 31) * 4;

    int K2 = K / 2;

    float acc[4][4][4];
    int i0, i1, i2;
    #pragma unroll
    for (i0 = 0; i0 < 4; i0++)
        #pragma unroll
        for (i1 = 0; i1 < 4; i1++)
            #pragma unroll
            for (i2 = 0; i2 < 4; i2++)
                acc[i0][i1][i2] = 0.0f;

    const uint32_t *ahp = AH + (row0 + arow) * (long)K2 + aw4;
    const uint32_t *alp = AL + (row0 + arow) * (long)K2 + aw4;
    const uint32_t *bhp = BH + (long)bkr * N + col0 + bnc;
    const uint32_t *blp = BL + (long)bkr * N + col0 + bnc;

    uint4 pah = *(const uint4 *)(ahp);
    uint4 pal = *(const uint4 *)(alp);
    uint4 pbh = *(const uint4 *)(bhp);
    uint4 pbl = *(const uint4 *)(blp);

    put_colstage(sm[0].AsH, sm[0].AsL, pah, pal, aw4, arow);
    put_rowstage(&sm[0], pbh, pbl, bkr, bnc);
    __syncthreads();

    int nsteps = K / 16;
    int s;
    for (s = 0; s < nsteps; s++) {
        int more = (s + 1 < nsteps) ? 1 : 0;
        if (more) {
            long ko = (long)(s + 1) * 8;
            pah = *(const uint4 *)(ahp + ko);
            pal = *(const uint4 *)(alp + ko);
            pbh = *(const uint4 *)(bhp + ko * N);
            pbl = *(const uint4 *)(blp + ko * N);
        }
        compute_stage(&sm[s & 1], acc, m0w, n0w, g, t);
        if (more) {
            put_colstage(sm[(s + 1) & 1].AsH, sm[(s + 1) & 1].AsL,
                         pah, pal, aw4, arow);
            put_rowstage(&sm[(s + 1) & 1], pbh, pbl, bkr, bnc);
            __syncthreads();
        }
    }

    float *cf = (Cf != 0) ? (Cf + zo * sCf) : (float *)0;
    uint32_t *chi = (Chi != 0) ? (Chi + zo * sC2) : (uint32_t *)0;
    uint32_t *clo = (Clo != 0) ? (Clo + zo * sC2) : (uint32_t *)0;
    int N2 = N / 2;

    int ma, na;
    #pragma unroll
    for (ma = 0; ma < 4; ma++) {
        long r = row0 + m0w + ma * 16 + g;
        #pragma unroll
        for (na = 0; na < 4; na++) {
            long c = col0 + n0w + na * 8 + 2 * t;
            float b0 = 0.0f;
            float b1 = 0.0f;
            if (bi != 0) {
                b0 = bi[c];
                b1 = bi[c + 1];
            }
            float v0 = acc[ma][na][0] + b0;
            float v1 = acc[ma][na][1] + b1;
            float w0 = acc[ma][na][2] + b0;
            float w1 = acc[ma][na][3] + b1;
            if (resid != 0) {
                v0 += resid[r * N + c];
                v1 += resid[r * N + c + 1];
                w0 += resid[(r + 8) * N + c];
                w1 += resid[(r + 8) * N + c + 1];
            }
            if (relu != 0) {
                v0 = fmaxf(v0, 0.0f);
                v1 = fmaxf(v1, 0.0f);
                w0 = fmaxf(w0, 0.0f);
                w1 = fmaxf(w1, 0.0f);
            }
            if (cf != 0) {
                cf[r * N + c]           = v0;
                cf[r * N + c + 1]       = v1;
                cf[(r + 8) * N + c]     = w0;
                cf[(r + 8) * N + c + 1] = w1;
            }
            if (cmode == 1) {
                uint32_t h0, l0, h1, l1;
                split_pair(v0, v1, h0, l0);
                split_pair(w0, w1, h1, l1);
                chi[r * N2 + c / 2]       = h0;
                clo[r * N2 + c / 2]       = l0;
                chi[(r + 8) * N2 + c / 2] = h1;
                clo[(r + 8) * N2 + c / 2] = l1;
            } else if (cmode == 2) {
                // B-type: pair rows (r, r+1); partner holds row r^1 (lane^4)
                float ov0 = __shfl_xor_sync(0xffffffffu, v0, 4);
                float ov1 = __shfl_xor_sync(0xffffffffu, v1, 4);
                float ow0 = __shfl_xor_sync(0xffffffffu, w0, 4);
                float ow1 = __shfl_xor_sync(0xffffffffu, w1, 4);
                if ((g & 1) == 0) {
                    uint32_t h0, l0, h1, l1, h2, l2, h3, l3;
                    split_pair(v0, ov0, h0, l0);
                    split_pair(v1, ov1, h1, l1);
                    split_pair(w0, ow0, h2, l2);
                    split_pair(w1, ow1, h3, l3);
                    long p0 = (r >> 1) * (long)N + c;
                    long p1 = ((r + 8) >> 1) * (long)N + c;
                    chi[p0]     = h0;
                    chi[p0 + 1] = h1;
                    clo[p0]     = l0;
                    clo[p0 + 1] = l1;
                    chi[p1]     = h2;
                    chi[p1 + 1] = h3;
                    clo[p1]     = l2;
                    clo[p1 + 1] = l3;
                }
            }
        }
    }
}

// ---------------- scores = (Q @ K^T)/sqrt(KD), causal block skip ------------
__global__ void __launch_bounds__(256) bf_qkt(
    const uint32_t *Qhi, const uint32_t *Qlo,
    const uint32_t *Khi, const uint32_t *Klo,
    float *SCg, float scale)
{
    __shared__ SmemTiles sm[2];

    if (blockIdx.x > blockIdx.y) return;
    long zo = (long)blockIdx.z * S_DIM * (KD_DIM / 2);
    const uint32_t *QH = Qhi + zo;
    const uint32_t *QL = Qlo + zo;
    const uint32_t *KH = Khi + zo;
    const uint32_t *KL = Klo + zo;
    float *C = SCg + (long)blockIdx.z * S_DIM * (long)S_DIM;

    int tid = threadIdx.x;
    int lane = tid & 31;
    int warp = tid >> 5;
    int g = lane >> 2;
    int t = lane & 3;
    int m0w = (warp >> 2) * 64;
    int n0w = (warp & 3) * 32;
    long row0 = (long)blockIdx.y * 128;
    long col0 = (long)blockIdx.x * 128;

    int arow = tid >> 1;
    int aw4 = (tid & 1) * 4;
    int K2 = KD_DIM / 2;

    float acc[4][4][4];
    int i0, i1, i2;
    #pragma unroll
    for (i0 = 0; i0 < 4; i0++)
        #pragma unroll
        for (i1 = 0; i1 < 4; i1++)
            #pragma unroll
            for (i2 = 0; i2 < 4; i2++)
                acc[i0][i1][i2] = 0.0f;

    const uint32_t *qhp = QH + (row0 + arow) * (long)K2 + aw4;
    const uint32_t *qlp = QL + (row0 + arow) * (long)K2 + aw4;
    const uint32_t *khp = KH + (col0 + arow) * (long)K2 + aw4;
    const uint32_t *klp = KL + (col0 + arow) * (long)K2 + aw4;

    uint4 pah = *(const uint4 *)(qhp);
    uint4 pal = *(const uint4 *)(qlp);
    uint4 pbh = *(const uint4 *)(khp);
    uint4 pbl = *(const uint4 *)(klp);

    put_colstage(sm[0].AsH, sm[0].AsL, pah, pal, aw4, arow);
    put_colstage(sm[0].BsH, sm[0].BsL, pbh, pbl, aw4, arow);
    __syncthreads();

    int nsteps = KD_DIM / 16;
    int s;
    for (s = 0; s < nsteps; s++) {
        int more = (s + 1 < nsteps) ? 1 : 0;
        if (more) {
            long ko = (long)(s + 1) * 8;
            pah = *(const uint4 *)(qhp + ko);
            pal = *(const uint4 *)(qlp + ko);
            pbh = *(const uint4 *)(khp + ko);
            pbl = *(const uint4 *)(klp + ko);
        }
        compute_stage(&sm[s & 1], acc, m0w, n0w, g, t);
        if (more) {
            put_colstage(sm[(s + 1) & 1].AsH, sm[(s + 1) & 1].AsL,
                         pah, pal, aw4, arow);
            put_colstage(sm[(s + 1) & 1].BsH, sm[(s + 1) & 1].BsL,
                         pbh, pbl, aw4, arow);
            __syncthreads();
        }
    }

    int ma, na;
    #pragma unroll
    for (ma = 0; ma < 4; ma++) {
        long r = row0 + m0w + ma * 16 + g;
        #pragma unroll
        for (na = 0; na < 4; na++) {
            long c = col0 + n0w + na * 8 + 2 * t;
            C[r * S_DIM + c]           = acc[ma][na][0] * scale;
            C[r * S_DIM + c + 1]       = acc[ma][na][1] * scale;
            C[(r + 8) * S_DIM + c]     = acc[ma][na][2] * scale;
            C[(r + 8) * S_DIM + c + 1] = acc[ma][na][3] * scale;
        }
    }
}

// ---------------- partial[z] = sum_{h in group z} attn[h] @ V[h] ------------
__global__ void __launch_bounds__(256) bf_attn_av(
    const uint32_t *Athi, const uint32_t *Atlo,
    const uint32_t *Vhi, const uint32_t *Vlo,
    float *Pg)
{
    __shared__ SmemTiles sm[2];

    int tid = threadIdx.x;
    int lane = tid & 31;
    int warp = tid >> 5;
    int g = lane >> 2;
    int t = lane & 3;
    int m0w = (warp >> 2) * 64;
    int n0w = (warp & 3) * 32;
    long row0 = (long)blockIdx.y * 128;
    long col0 = (long)blockIdx.x * 128;

    int arow = tid >> 1;
    int aw4 = (tid & 1) * 4;
    int bkr = tid >> 5;
    int bnc = (tid & 31) * 4;

    int nk = ((int)blockIdx.y + 1) * 8;
    int total = 4 * nk;
    int h0 = (int)blockIdx.z * 4;
    long S2 = S_DIM / 2;

    float acc[4][4][4];
    int i0, i1, i2;
    #pragma unroll
    for (i0 = 0; i0 < 4; i0++)
        #pragma unroll
        for (i1 = 0; i1 < 4; i1++)
            #pragma unroll
            for (i2 = 0; i2 < 4; i2++)
                acc[i0][i1][i2] = 0.0f;

    uint4 pah, pal, pbh, pbl;
    {
        long ab = ((long)h0 * S_DIM + row0 + arow) * S2 + aw4;
        long bb = (long)h0 * S2 * E_DIM + (long)bkr * E_DIM + col0 + bnc;
        pah = *(const uint4 *)(Athi + ab);
        pal = *(const uint4 *)(Atlo + ab);
        pbh = *(const uint4 *)(Vhi + bb);
        pbl = *(const uint4 *)(Vlo + bb);
    }
    put_colstage(sm[0].AsH, sm[0].AsL, pah, pal, aw4, arow);
    put_rowstage(&sm[0], pbh, pbl, bkr, bnc);
    __syncthreads();

    int h = h0;
    int ks = 0;
    int it;
    for (it = 0; it < total; it++) {
        int more = (it + 1 < total) ? 1 : 0;
        int h2 = h;
        int k2 = ks + 1;
        if (k2 == nk) {
            k2 = 0;
            h2 = h2 + 1;
        }
        if (more) {
            long ab = ((long)h2 * S_DIM + row0 + arow) * S2 + k2 * 8 + aw4;
            long bb = ((long)h2 * S2 + (long)k2 * 8 + bkr) * E_DIM + col0 + bnc;
            pah = *(const uint4 *)(Athi + ab);
            pal = *(const uint4 *)(Atlo + ab);
            pbh = *(const uint4 *)(Vhi + bb);
            pbl = *(const uint4 *)(Vlo + bb);
        }
        compute_stage(&sm[it & 1], acc, m0w, n0w, g, t);
        if (more) {
            put_colstage(sm[(it + 1) & 1].AsH, sm[(it + 1) & 1].AsL,
                         pah, pal, aw4, arow);
            put_rowstage(&sm[(it + 1) & 1], pbh, pbl, bkr, bnc);
            __syncthreads();
        }
        h = h2;
        ks = k2;
    }

    float *P = Pg + (long)blockIdx.z * S_DIM * E_DIM;
    int ma, na;
    #pragma unroll
    for (ma = 0; ma < 4; ma++) {
        long r = row0 + m0w + ma * 16 + g;
        #pragma unroll
        for (na = 0; na < 4; na++) {
            long c = col0 + n0w + na * 8 + 2 * t;
            P[r * E_DIM + c]           = acc[ma][na][0];
            P[r * E_DIM + c + 1]       = acc[ma][na][1];
            P[(r + 8) * E_DIM + c]     = acc[ma][na][2];
            P[(r + 8) * E_DIM + c + 1] = acc[ma][na][3];
        }
    }
}

// py = x + p0 + p1 + p2 + p3 (fixed order, deterministic)
__global__ void __launch_bounds__(256) reduce4(
    const float *x, const float *p, float *py)
{
    long stride = (long)gridDim.x * 256;
    long i;
    for (i = (long)blockIdx.x * 256 + threadIdx.x; i < NTOT; i += stride) {
        float v = x[i];
        v += p[i];
        v += p[NTOT + i];
        v += p[2 * NTOT + i];
        v += p[3 * NTOT + i];
        py[i] = v;
    }
}

// ---------------- causal row softmax -> split attn (hi/lo pairs) ------------
__global__ void __launch_bounds__(256) softmax_causal(
    const float *sc, uint32_t *athi, uint32_t *atlo)
{
    __shared__ float buf[S_DIM];
    __shared__ float red[256];

    int s = blockIdx.x;
    int h = blockIdx.y;
    const float *row = sc + ((long)h * S_DIM + s) * (long)S_DIM;
    long out2 = ((long)h * S_DIM + s) * (long)(S_DIM / 2);
    int tid = threadIdx.x;
    int len = s + 1;
    int i;
    int st;

    float lmax = -INFINITY;
    for (i = tid; i < len; i += 256) {
        float v = row[i];
        buf[i] = v;
        lmax = fmaxf(lmax, v);
    }
    red[tid] = lmax;
    __syncthreads();
    for (st = 128; st > 0; st >>= 1) {
        if (tid < st) red[tid] = fmaxf(red[tid], red[tid + st]);
        __syncthreads();
    }
    float m = red[0];
    __syncthreads();

    float lsum = 0.0f;
    for (i = tid; i < len; i += 256) {
        float e = __expf(buf[i] - m);
        buf[i] = e;
        lsum += e;
    }
    red[tid] = lsum;
    __syncthreads();
    for (st = 128; st > 0; st >>= 1) {
        if (tid < st) red[tid] = red[tid] + red[tid + st];
        __syncthreads();
    }
    float inv = 1.0f / red[0];
    for (i = tid; i < S_DIM / 2; i += 256) {
        int i0 = 2 * i;
        int i1 = 2 * i + 1;
        float a = (i0 < len) ? buf[i0] * inv : 0.0f;
        float b = (i1 < len) ? buf[i1] * inv : 0.0f;
        uint32_t hh, ll;
        split_pair(a, b, hh, ll);
        athi[out2 + i] = hh;
        atlo[out2 + i] = ll;
    }
}

// ---------------- global LayerNorm ------------------------------------------
__global__ void __launch_bounds__(256) ln_reduce(const float *y, double *part)
{
    __shared__ double sd[256];
    __shared__ double sq[256];

    double s = 0.0;
    double ss = 0.0;
    long stride = (long)gridDim.x * 256;
    long i;
    int st;
    for (i = (long)blockIdx.x * 256 + threadIdx.x; i < NTOT; i += stride) {
        double v = (double)y[i];
        s += v;
        ss += v * v;
    }
    sd[threadIdx.x] = s;
    sq[threadIdx.x] = ss;
    __syncthreads();
    for (st = 128; st > 0; st >>= 1) {
        if (threadIdx.x < st) {
            sd[threadIdx.x] = sd[threadIdx.x] + sd[threadIdx.x + st];
            sq[threadIdx.x] = sq[threadIdx.x] + sq[threadIdx.x + st];
        }
        __syncthreads();
    }
    if (threadIdx.x == 0) {
        part[blockIdx.x] = sd[0];
        part[1024 + blockIdx.x] = sq[0];
    }
}

__global__ void __launch_bounds__(256) ln_finalize(const double *part, float *stats)
{
    __shared__ double sd[256];
    __shared__ double sq[256];

    double s = 0.0;
    double ss = 0.0;
    int i;
    int st;
    for (i = threadIdx.x; i < 1024; i += 256) {
        s += part[i];
        ss += part[1024 + i];
    }
    sd[threadIdx.x] = s;
    sq[threadIdx.x] = ss;
    __syncthreads();
    for (st = 128; st > 0; st >>= 1) {
        if (threadIdx.x < st) {
            sd[threadIdx.x] = sd[threadIdx.x] + sd[threadIdx.x + st];
            sq[threadIdx.x] = sq[threadIdx.x] + sq[threadIdx.x + st];
        }
        __syncthreads();
    }
    if (threadIdx.x == 0) {
        double mean = sd[0] / (double)NTOT;
        double var = sq[0] / (double)NTOT - mean * mean;
        stats[0] = (float)mean;
        stats[1] = (float)(1.0 / sqrt(var + (double)EPS));
    }
}

__global__ void __launch_bounds__(256) ln_apply(
    const float *y, const float *g, const float *b,
    const float *st, float *of32, uint32_t *ohi, uint32_t *olo)
{
    float m = st[0];
    float is = st[1];
    long stride = (long)gridDim.x * 256;
    long i;
    for (i = (long)blockIdx.x * 256 + threadIdx.x; i < NTOT / 2; i += stride) {
        long i0 = 2 * i;
        long i1 = 2 * i + 1;
        float v0 = (y[i0] - m) * is * g[i0] + b[i0];
        float v1 = (y[i1] - m) * is * g[i1] + b[i1];
        if (of32 != 0) {
            of32[i0] = v0;
            of32[i1] = v1;
        }
        if (ohi != 0) {
            uint32_t hh, ll;
            split_pair(v0, v1, hh, ll);
            ohi[i] = hh;
            olo[i] = ll;
        }
    }
}

// ---------------- host orchestration ----------------------------------------
extern "C" void kernel_launch(void* const* d_in, const int* in_sizes, int n_in,
                              void* d_out, int out_size)
{
    const float *x  = (const float *)d_in[0];
    const float *Wq = (const float *)d_in[1];
    const float *bq = (const float *)d_in[2];
    const float *Wk = (const float *)d_in[3];
    const float *bk = (const float *)d_in[4];
    const float *Wv = (const float *)d_in[5];
    const float *bv = (const float *)d_in[6];
    const float *lg = (const float *)d_in[7];
    const float *lb = (const float *)d_in[8];
    const float *W1 = (const float *)d_in[9];
    const float *b1 = (const float *)d_in[10];
    const float *W2 = (const float *)d_in[11];
    const float *b2 = (const float *)d_in[12];
    float *out = (float *)d_out;

    void *pv_[32];
    cudaGetSymbolAddress(&pv_[0],  g_sc);
    cudaGetSymbolAddress(&pv_[1],  g_y);
    cudaGetSymbolAddress(&pv_[2],  g_h);
    cudaGetSymbolAddress(&pv_[3],  g_pt);
    cudaGetSymbolAddress(&pv_[4],  g_part);
    cudaGetSymbolAddress(&pv_[5],  g_stats);
    cudaGetSymbolAddress(&pv_[6],  g_xhi);
    cudaGetSymbolAddress(&pv_[7],  g_xlo);
    cudaGetSymbolAddress(&pv_[8],  g_wqhi);
    cudaGetSymbolAddress(&pv_[9],  g_wqlo);
    cudaGetSymbolAddress(&pv_[10], g_wkhi);
    cudaGetSymbolAddress(&pv_[11], g_wklo);
    cudaGetSymbolAddress(&pv_[12], g_wvhi);
    cudaGetSymbolAddress(&pv_[13], g_wvlo);
    cudaGetSymbolAddress(&pv_[14], g_w1hi);
    cudaGetSymbolAddress(&pv_[15], g_w1lo);
    cudaGetSymbolAddress(&pv_[16], g_w2hi);
    cudaGetSymbolAddress(&pv_[17], g_w2lo);
    cudaGetSymbolAddress(&pv_[18], g_qhi);
    cudaGetSymbolAddress(&pv_[19], g_qlo);
    cudaGetSymbolAddress(&pv_[20], g_khi);
    cudaGetSymbolAddress(&pv_[21], g_klo);
    cudaGetSymbolAddress(&pv_[22], g_vhi);
    cudaGetSymbolAddress(&pv_[23], g_vlo);
    cudaGetSymbolAddress(&pv_[24], g_athi);
    cudaGetSymbolAddress(&pv_[25], g_atlo);
    cudaGetSymbolAddress(&pv_[26], g_hhi);
    cudaGetSymbolAddress(&pv_[27], g_hlo);
    cudaGetSymbolAddress(&pv_[28], g_ffhi);
    cudaGetSymbolAddress(&pv_[29], g_fflo);

    float *psc    = (float *)pv_[0];
    float *py     = (float *)pv_[1];
    float *ph     = (float *)pv_[2];
    float *ppt    = (float *)pv_[3];
    double *ppart = (double *)pv_[4];
    float *pstats = (float *)pv_[5];
    uint32_t *xhi = (uint32_t *)pv_[6],  *xlo = (uint32_t *)pv_[7];
    uint32_t *wqh = (uint32_t *)pv_[8],  *wql = (uint32_t *)pv_[9];
    uint32_t *wkh = (uint32_t *)pv_[10], *wkl = (uint32_t *)pv_[11];
    uint32_t *wvh = (uint32_t *)pv_[12], *wvl = (uint32_t *)pv_[13];
    uint32_t *w1h = (uint32_t *)pv_[14], *w1l = (uint32_t *)pv_[15];
    uint32_t *w2h = (uint32_t *)pv_[16], *w2l = (uint32_t *)pv_[17];
    uint32_t *qh  = (uint32_t *)pv_[18], *ql  = (uint32_t *)pv_[19];
    uint32_t *kh  = (uint32_t *)pv_[20], *kl  = (uint32_t *)pv_[21];
    uint32_t *vh  = (uint32_t *)pv_[22], *vl  = (uint32_t *)pv_[23];
    uint32_t *ath = (uint32_t *)pv_[24], *atl = (uint32_t *)pv_[25];
    uint32_t *hh  = (uint32_t *)pv_[26], *hl  = (uint32_t *)pv_[27];
    uint32_t *ffh = (uint32_t *)pv_[28], *ffl = (uint32_t *)pv_[29];

    dim3 blk(256, 1, 1);
    float scale = 1.0f / sqrtf((float)KD_DIM);

    // -------- operand splits (launches 0-4; W2 split deferred) --------
    split_rowpair<<<2048, blk>>>(x, xhi, xlo, NTOT / 2);
    split_colpair3d<<<dim3(KD_DIM / 256 + 1, E_DIM / 2, H_DIM), blk>>>(
        Wq, wqh, wql, E_DIM, KD_DIM);
    split_colpair3d<<<dim3(KD_DIM / 256 + 1, E_DIM / 2, H_DIM), blk>>>(
        Wk, wkh, wkl, E_DIM, KD_DIM);
    split_colpair3d<<<dim3(E_DIM / 256, E_DIM / 2, H_DIM), blk>>>(
        Wv, wvh, wvl, E_DIM, E_DIM);
    split_colpair3d<<<dim3(FF_DIM / 256, E_DIM / 2, 1), blk>>>(
        W1, w1h, w1l, E_DIM, FF_DIM);

    // -------- Q/K projections (A-split outputs) — launch 5 = bf_gemm -------
    {
        dim3 gq(1, S_DIM / 128, H_DIM);
        bf_gemm<<<gq, blk>>>(xhi, xlo, wqh, wql, bq,
            (const float *)0, (float *)0, qh, ql, 1, E_DIM, KD_DIM,
            0L, (long)(E_DIM / 2) * KD_DIM, (long)KD_DIM,
            0L, (long)S_DIM * (KD_DIM / 2), 0);
        bf_gemm<<<gq, blk>>>(xhi, xlo, wkh, wkl, bk,
            (const float *)0, (float *)0, kh, kl, 1, E_DIM, KD_DIM,
            0L, (long)(E_DIM / 2) * KD_DIM, (long)KD_DIM,
            0L, (long)S_DIM * (KD_DIM / 2), 0);
    }
    // -------- V projection: fused B-type split output --------
    {
        dim3 gv(E_DIM / 128, S_DIM / 128, H_DIM);
        bf_gemm<<<gv, blk>>>(xhi, xlo, wvh, wvl, bv,
            (const float *)0, (float *)0, vh, vl, 2, E_DIM, E_DIM,
            0L, (long)(E_DIM / 2) * E_DIM, (long)E_DIM,
            0L, (long)(S_DIM / 2) * E_DIM, 0);
    }

    // -------- scores + causal softmax (fused attn split) --------
    {
        dim3 gs(S_DIM / 128, S_DIM / 128, H_DIM);
        bf_qkt<<<gs, blk>>>(qh, ql, kh, kl, psc, scale);
    }
    {
        dim3 gsm(S_DIM, H_DIM, 1);
        softmax_causal<<<gsm, blk>>>(psc, ath, atl);
    }

    // -------- attn @ V: 4 balanced head-groups + deterministic reduce -------
    {
        dim3 ga(E_DIM / 128, S_DIM / 128, 4);
        bf_attn_av<<<ga, blk>>>(ath, atl, vh, vl, ppt);
        reduce4<<<2048, blk>>>(x, ppt, py);
    }

    // -------- LN1 --------
    ln_reduce<<<1024, blk>>>(py, ppart);
    ln_finalize<<<1, blk>>>(ppart, pstats);
    ln_apply<<<2048, blk>>>(py, lg, lb, pstats, ph, hh, hl);

    // -------- deferred W2 split + FFN --------
    split_colpair3d<<<dim3(E_DIM / 256, FF_DIM / 2, 1), blk>>>(
        W2, w2h, w2l, FF_DIM, E_DIM);
    {
        dim3 g1(FF_DIM / 128, S_DIM / 128, 1);
        bf_gemm<<<g1, blk>>>(hh, hl, w1h, w1l, b1,
            (const float *)0, (float *)0, ffh, ffl, 1, E_DIM, FF_DIM,
            0L, 0L, 0L, 0L, 0L, 1);
        dim3 g2(E_DIM / 128, S_DIM / 128, 1);
        bf_gemm<<<g2, blk>>>(ffh, ffl, w2h, w2l, b2, ph,
            py, (uint32_t *)0, (uint32_t *)0, 0, FF_DIM, E_DIM,
            0L, 0L, 0L, (long)S_DIM * E_DIM, 0L, 0);
    }

    // -------- LN2 -> output --------
    ln_reduce<<<1024, blk>>>(py, ppart);
    ln_finalize<<<1, blk>>>(ppart, pstats);
    ln_apply<<<2048, blk>>>(py, lg, lb, pstats, out, (uint32_t *)0,
                            (uint32_t *)0);
}

// round 17
// speedup vs baseline: 1.2854x; 1.0450x over previous
#include <cuda_runtime.h>
#include <cuda_bf16.h>
#include <stdint.h>
#include <math.h>

// Problem dims
#define S_DIM 2048
#define E_DIM 2048
#define H_DIM 16
#define KD_DIM 128
#define FF_DIM 8192
#define EPS 1e-5f
#define NTOT (2048L * 2048L)

// ---------------- scratch (device globals; no allocations allowed) ----------
__device__ float    g_sc [(long)H_DIM * S_DIM * S_DIM];
__device__ float    g_y  [(long)S_DIM * E_DIM];
__device__ float    g_h  [(long)S_DIM * E_DIM];
__device__ float    g_pt [4L * S_DIM * E_DIM];
__device__ double   g_part[2048];
__device__ float    g_stats[2];
// paired-bf16 hi/lo operand buffers (uint32 = bf16x2)
__device__ uint32_t g_xhi [(long)S_DIM * E_DIM / 2];
__device__ uint32_t g_xlo [(long)S_DIM * E_DIM / 2];
__device__ uint32_t g_wqhi[(long)H_DIM * E_DIM * KD_DIM / 2];
__device__ uint32_t g_wqlo[(long)H_DIM * E_DIM * KD_DIM / 2];
__device__ uint32_t g_wkhi[(long)H_DIM * E_DIM * KD_DIM / 2];
__device__ uint32_t g_wklo[(long)H_DIM * E_DIM * KD_DIM / 2];
__device__ uint32_t g_wvhi[(long)H_DIM * E_DIM * E_DIM / 2];
__device__ uint32_t g_wvlo[(long)H_DIM * E_DIM * E_DIM / 2];
__device__ uint32_t g_w1hi[(long)E_DIM * FF_DIM / 2];
__device__ uint32_t g_w1lo[(long)E_DIM * FF_DIM / 2];
__device__ uint32_t g_w2hi[(long)FF_DIM * E_DIM / 2];
__device__ uint32_t g_w2lo[(long)FF_DIM * E_DIM / 2];
__device__ uint32_t g_qhi [(long)H_DIM * S_DIM * KD_DIM / 2];
__device__ uint32_t g_qlo [(long)H_DIM * S_DIM * KD_DIM / 2];
__device__ uint32_t g_khi [(long)H_DIM * S_DIM * KD_DIM / 2];
__device__ uint32_t g_klo [(long)H_DIM * S_DIM * KD_DIM / 2];
__device__ uint32_t g_vhi [(long)H_DIM * S_DIM * E_DIM / 2];
__device__ uint32_t g_vlo [(long)H_DIM * S_DIM * E_DIM / 2];
__device__ uint32_t g_athi[(long)H_DIM * S_DIM * S_DIM / 2];
__device__ uint32_t g_atlo[(long)H_DIM * S_DIM * S_DIM / 2];
__device__ uint32_t g_hhi [(long)S_DIM * E_DIM / 2];
__device__ uint32_t g_hlo [(long)S_DIM * E_DIM / 2];
__device__ uint32_t g_ffhi[(long)S_DIM * FF_DIM / 2];
__device__ uint32_t g_fflo[(long)S_DIM * FF_DIM / 2];

// ===================== helpers ==============================================
__device__ __forceinline__ void split_pair(float f0, float f1,
                                           uint32_t &hi, uint32_t &lo)
{
    __nv_bfloat16 h0 = __float2bfloat16_rn(f0);
    __nv_bfloat16 h1 = __float2bfloat16_rn(f1);
    __nv_bfloat16 l0 = __float2bfloat16_rn(f0 - __bfloat162float(h0));
    __nv_bfloat16 l1 = __float2bfloat16_rn(f1 - __bfloat162float(h1));
    unsigned short u0 = __bfloat16_as_ushort(h0);
    unsigned short u1 = __bfloat16_as_ushort(h1);
    unsigned short w0 = __bfloat16_as_ushort(l0);
    unsigned short w1 = __bfloat16_as_ushort(l1);
    hi = (uint32_t)u0 | ((uint32_t)u1 << 16);
    lo = (uint32_t)w0 | ((uint32_t)w1 << 16);
}

__device__ __forceinline__ uint32_t s2u(const void *p)
{
    uint32_t a;
    asm("{ .reg .u64 t; cvta.to.shared.u64 t, %1; cvt.u32.u64 %0, t; }"
        : "=r"(a) : "l"(p));
    return a;
}

__device__ __forceinline__ void cpa16(uint32_t dst, const uint32_t *src)
{
    asm volatile("cp.async.cg.shared.global [%0], [%1], 16;"
                 :: "r"(dst), "l"(src));
}
__device__ __forceinline__ void cp_commit(void)
{
    asm volatile("cp.async.commit_group;");
}
__device__ __forceinline__ void cp_wait0(void)
{
    asm volatile("cp.async.wait_group 0;" ::: "memory");
}

// split fp32 (adjacent pairs) -> hi/lo words (A-type)
__global__ void __launch_bounds__(256) split_rowpair(
    const float *in, uint32_t *hi, uint32_t *lo, long nwords)
{
    long stride = (long)gridDim.x * 256;
    long i;
    for (i = (long)blockIdx.x * 256 + threadIdx.x; i < nwords; i += stride) {
        float a = in[2 * i];
        float b = in[2 * i + 1];
        uint32_t h, l;
        split_pair(a, b, h, l);
        hi[i] = h;
        lo[i] = l;
    }
}

// split fp32 X[batch][K][N] pairing along K -> word[(b)(k/2)(n)] (B-type).
__global__ void __launch_bounds__(256) split_colpair3d(
    const float *in, uint32_t *hi, uint32_t *lo, int K, int N)
{
    int n = (int)blockIdx.x * 256 + (int)threadIdx.x;
    if (n >= N) return;
    long k2 = (long)blockIdx.y;
    long b = (long)blockIdx.z;
    const float *base = in + b * (long)K * N;
    float x0 = base[(2 * k2) * (long)N + n];
    float x1 = base[(2 * k2 + 1) * (long)N + n];
    uint32_t h, l;
    split_pair(x0, x1, h, l);
    long o = b * (long)(K / 2) * N + k2 * N + n;
    hi[o] = h;
    lo[o] = l;
}

// ===================== cp.async bf16-pair HMMA engine =======================
// 256 threads, block tile 128x128, warp grid 2x4, warp tile 64x32 (R9-proven).
// A-tile smem: [128 rows][12 words] (8 data + 4 pad); fragment reads at
// (12g+t)%32 - conflict-free. B-tile smem: [8 k2][136 words] (proven).
// Double buffer; copies for s+1 issued after stage-s barrier (hazard-safe),
// overlap compute(s).
//
// word offsets within one stage:
//   bt-kernels: AH 0, AL 1536, BH 3072, BL 4160; stage = 5248 words
//   qkt:        AH 0, AL 1536, BH 3072, BL 4608; stage = 6144 words
#define WSS   5248
#define QSS   6144
#define SM_BT (2 * 5248 * 4)
#define SM_QK (2 * 6144 * 4)

__device__ __forceinline__ void mma16816(float *c, const uint32_t *a,
                                         const uint32_t *b)
{
    asm volatile(
        "mma.sync.aligned.m16n8k16.row.col.f32.bf16.bf16.f32 "
        "{%0,%1,%2,%3},{%4,%5,%6,%7},{%8,%9},{%0,%1,%2,%3};\n"
        : "+f"(c[0]), "+f"(c[1]), "+f"(c[2]), "+f"(c[3])
        : "r"(a[0]), "r"(a[1]), "r"(a[2]), "r"(a[3]), "r"(b[0]), "r"(b[1]));
}

// one k16 step, 64x32 warp tile, A [128][12], B [8][136]
__device__ __forceinline__ void compute_bt(const uint32_t *p,
    float acc[4][4][4], int m0w, int n0w, int g, int t)
{
    const uint32_t *AH = p;
    const uint32_t *AL = p + 1536;
    const uint32_t *BH = p + 3072;
    const uint32_t *BL = p + 4160;
    uint32_t bh[4][2];
    uint32_t bl[4][2];
    int na, ma;
    #pragma unroll
    for (na = 0; na < 4; na++) {
        int c = n0w + na * 8 + g;
        bh[na][0] = BH[t * 136 + c];
        bh[na][1] = BH[(t + 4) * 136 + c];
        bl[na][0] = BL[t * 136 + c];
        bl[na][1] = BL[(t + 4) * 136 + c];
    }
    #pragma unroll
    for (ma = 0; ma < 4; ma++) {
        int r0 = m0w + ma * 16 + g;
        uint32_t ah[4];
        uint32_t al[4];
        ah[0] = AH[r0 * 12 + t];
        ah[1] = AH[(r0 + 8) * 12 + t];
        ah[2] = AH[r0 * 12 + t + 4];
        ah[3] = AH[(r0 + 8) * 12 + t + 4];
        al[0] = AL[r0 * 12 + t];
        al[1] = AL[(r0 + 8) * 12 + t];
        al[2] = AL[r0 * 12 + t + 4];
        al[3] = AL[(r0 + 8) * 12 + t + 4];
        #pragma unroll
        for (na = 0; na < 4; na++) {
            mma16816(acc[ma][na], ah, bh[na]);
            mma16816(acc[ma][na], ah, bl[na]);
            mma16816(acc[ma][na], al, bh[na]);
        }
    }
}

// one k16 step, 64x32 warp tile, A [128][12], B [128][12] (QK^T)
__device__ __forceinline__ void compute_at(const uint32_t *p,
    float acc[4][4][4], int m0w, int n0w, int g, int t)
{
    const uint32_t *AH = p;
    const uint32_t *AL = p + 1536;
    const uint32_t *BH = p + 3072;
    const uint32_t *BL = p + 4608;
    uint32_t bh[4][2];
    uint32_t bl[4][2];
    int na, ma;
    #pragma unroll
    for (na = 0; na < 4; na++) {
        int c = n0w + na * 8 + g;
        bh[na][0] = BH[c * 12 + t];
        bh[na][1] = BH[c * 12 + t + 4];
        bl[na][0] = BL[c * 12 + t];
        bl[na][1] = BL[c * 12 + t + 4];
    }
    #pragma unroll
    for (ma = 0; ma < 4; ma++) {
        int r0 = m0w + ma * 16 + g;
        uint32_t ah[4];
        uint32_t al[4];
        ah[0] = AH[r0 * 12 + t];
        ah[1] = AH[(r0 + 8) * 12 + t];
        ah[2] = AH[r0 * 12 + t + 4];
        ah[3] = AH[(r0 + 8) * 12 + t + 4];
        al[0] = AL[r0 * 12 + t];
        al[1] = AL[(r0 + 8) * 12 + t];
        al[2] = AL[r0 * 12 + t + 4];
        al[3] = AL[(r0 + 8) * 12 + t + 4];
        #pragma unroll
        for (na = 0; na < 4; na++) {
            mma16816(acc[ma][na], ah, bh[na]);
            mma16816(acc[ma][na], ah, bl[na]);
            mma16816(acc[ma][na], al, bh[na]);
        }
    }
}

// ---------------- C = A @ B from pre-split operands -------------------------
// A: A-type words [M][K/2] (+z*sA2). B: B-type words [K/2][N] (+z*sB2).
// cmode: 0 = none, 1 = A-type split out (Chi/Clo), 2 = B-type split out.
__global__ void __launch_bounds__(256) bf_gemm(
    const uint32_t *Ahi, const uint32_t *Alo,
    const uint32_t *Bhi, const uint32_t *Blo,
    const float *bias, const float *resid,
    float *Cf, uint32_t *Chi, uint32_t *Clo, int cmode,
    int K, int N,
    long sA2, long sB2, long sBias, long sCf, long sC2, int relu)
{
    extern __shared__ uint32_t dsw[];
    uint32_t sb = s2u(dsw);

    long zo = (long)blockIdx.z;
    const float *bi = (bias != 0) ? (bias + zo * sBias) : (const float *)0;

    int tid = threadIdx.x;
    int lane = tid & 31;
    int warp = tid >> 5;
    int g = lane >> 2;
    int t = lane & 3;
    int m0w = (warp >> 2) * 64;
    int n0w = (warp & 3) * 32;
    long row0 = (long)blockIdx.y * 128;
    long col0 = (long)blockIdx.x * 128;

    int K2 = K / 2;
    int arow = tid >> 1;
    int ahalf = (tid & 1) * 4;
    int bk2 = tid >> 5;
    int bnc = (tid & 31) * 4;

    const uint32_t *AHr = Ahi + zo * sA2 + (row0 + arow) * (long)K2 + ahalf;
    const uint32_t *ALr = Alo + zo * sA2 + (row0 + arow) * (long)K2 + ahalf;
    const uint32_t *BHr = Bhi + zo * sB2 + (long)bk2 * N + col0 + bnc;
    const uint32_t *BLr = Blo + zo * sB2 + (long)bk2 * N + col0 + bnc;

    uint32_t adw = (uint32_t)(arow * 12 + ahalf);
    uint32_t bdw = (uint32_t)(bk2 * 136 + bnc);

    float acc[4][4][4];
    int i0, i1, i2;
    #pragma unroll
    for (i0 = 0; i0 < 4; i0++)
        #pragma unroll
        for (i1 = 0; i1 < 4; i1++)
            #pragma unroll
            for (i2 = 0; i2 < 4; i2++)
                acc[i0][i1][i2] = 0.0f;

    int nsteps = K / 16;
    int s;
    // prologue: stage 0
    cpa16(sb + adw * 4, AHr);
    cpa16(sb + (1536 + adw) * 4, ALr);
    cpa16(sb + (3072 + bdw) * 4, BHr);
    cpa16(sb + (4160 + bdw) * 4, BLr);
    cp_commit();

    for (s = 0; s < nsteps; s++) {
        cp_wait0();
        __syncthreads();
        if (s + 1 < nsteps) {
            uint32_t bw = ((uint32_t)((s + 1) & 1)) * WSS;
            long ka = (long)(s + 1) * 8;
            long kb = ka * N;
            cpa16(sb + (bw + adw) * 4, AHr + ka);
            cpa16(sb + (bw + 1536 + adw) * 4, ALr + ka);
            cpa16(sb + (bw + 3072 + bdw) * 4, BHr + kb);
            cpa16(sb + (bw + 4160 + bdw) * 4, BLr + kb);
            cp_commit();
        }
        compute_bt(dsw + (s & 1) * WSS, acc, m0w, n0w, g, t);
    }

    float *cf = (Cf != 0) ? (Cf + zo * sCf) : (float *)0;
    uint32_t *chi = (Chi != 0) ? (Chi + zo * sC2) : (uint32_t *)0;
    uint32_t *clo = (Clo != 0) ? (Clo + zo * sC2) : (uint32_t *)0;
    int N2 = N / 2;

    int ma, na;
    #pragma unroll
    for (ma = 0; ma < 4; ma++) {
        long r = row0 + m0w + ma * 16 + g;
        #pragma unroll
        for (na = 0; na < 4; na++) {
            long c = col0 + n0w + na * 8 + 2 * t;
            float b0 = 0.0f;
            float b1 = 0.0f;
            if (bi != 0) {
                b0 = bi[c];
                b1 = bi[c + 1];
            }
            float v0 = acc[ma][na][0] + b0;
            float v1 = acc[ma][na][1] + b1;
            float w0 = acc[ma][na][2] + b0;
            float w1 = acc[ma][na][3] + b1;
            if (resid != 0) {
                v0 += resid[r * N + c];
                v1 += resid[r * N + c + 1];
                w0 += resid[(r + 8) * N + c];
                w1 += resid[(r + 8) * N + c + 1];
            }
            if (relu != 0) {
                v0 = fmaxf(v0, 0.0f);
                v1 = fmaxf(v1, 0.0f);
                w0 = fmaxf(w0, 0.0f);
                w1 = fmaxf(w1, 0.0f);
            }
            if (cf != 0) {
                cf[r * N + c]           = v0;
                cf[r * N + c + 1]       = v1;
                cf[(r + 8) * N + c]     = w0;
                cf[(r + 8) * N + c + 1] = w1;
            }
            if (cmode == 1) {
                uint32_t h0, l0, h1, l1;
                split_pair(v0, v1, h0, l0);
                split_pair(w0, w1, h1, l1);
                chi[r * N2 + c / 2]       = h0;
                clo[r * N2 + c / 2]       = l0;
                chi[(r + 8) * N2 + c / 2] = h1;
                clo[(r + 8) * N2 + c / 2] = l1;
            } else if (cmode == 2) {
                float ov0 = __shfl_xor_sync(0xffffffffu, v0, 4);
                float ov1 = __shfl_xor_sync(0xffffffffu, v1, 4);
                float ow0 = __shfl_xor_sync(0xffffffffu, w0, 4);
                float ow1 = __shfl_xor_sync(0xffffffffu, w1, 4);
                if ((g & 1) == 0) {
                    uint32_t h0, l0, h1, l1, h2, l2, h3, l3;
                    split_pair(v0, ov0, h0, l0);
                    split_pair(v1, ov1, h1, l1);
                    split_pair(w0, ow0, h2, l2);
                    split_pair(w1, ow1, h3, l3);
                    long p0 = (r >> 1) * (long)N + c;
                    long p1 = ((r + 8) >> 1) * (long)N + c;
                    chi[p0]     = h0;
                    chi[p0 + 1] = h1;
                    clo[p0]     = l0;
                    clo[p0 + 1] = l1;
                    chi[p1]     = h2;
                    chi[p1 + 1] = h3;
                    clo[p1]     = l2;
                    clo[p1 + 1] = l3;
                }
            }
        }
    }
}

// ---------------- scores = (Q @ K^T)/sqrt(KD), causal block skip ------------
__global__ void __launch_bounds__(256) bf_qkt(
    const uint32_t *Qhi, const uint32_t *Qlo,
    const uint32_t *Khi, const uint32_t *Klo,
    float *SCg, float scale)
{
    extern __shared__ uint32_t dsw[];

    if (blockIdx.x > blockIdx.y) return;
    uint32_t sb = s2u(dsw);

    long zo = (long)blockIdx.z * S_DIM * (KD_DIM / 2);
    float *C = SCg + (long)blockIdx.z * S_DIM * (long)S_DIM;

    int tid = threadIdx.x;
    int lane = tid & 31;
    int warp = tid >> 5;
    int g = lane >> 2;
    int t = lane & 3;
    int m0w = (warp >> 2) * 64;
    int n0w = (warp & 3) * 32;
    long row0 = (long)blockIdx.y * 128;
    long col0 = (long)blockIdx.x * 128;

    int K2 = KD_DIM / 2;
    int arow = tid >> 1;
    int ahalf = (tid & 1) * 4;

    const uint32_t *QHr = Qhi + zo + (row0 + arow) * (long)K2 + ahalf;
    const uint32_t *QLr = Qlo + zo + (row0 + arow) * (long)K2 + ahalf;
    const uint32_t *KHr = Khi + zo + (col0 + arow) * (long)K2 + ahalf;
    const uint32_t *KLr = Klo + zo + (col0 + arow) * (long)K2 + ahalf;

    uint32_t adw = (uint32_t)(arow * 12 + ahalf);

    float acc[4][4][4];
    int i0, i1, i2;
    #pragma unroll
    for (i0 = 0; i0 < 4; i0++)
        #pragma unroll
        for (i1 = 0; i1 < 4; i1++)
            #pragma unroll
            for (i2 = 0; i2 < 4; i2++)
                acc[i0][i1][i2] = 0.0f;

    int nsteps = KD_DIM / 16;
    int s;
    cpa16(sb + adw * 4, QHr);
    cpa16(sb + (1536 + adw) * 4, QLr);
    cpa16(sb + (3072 + adw) * 4, KHr);
    cpa16(sb + (4608 + adw) * 4, KLr);
    cp_commit();

    for (s = 0; s < nsteps; s++) {
        cp_wait0();
        __syncthreads();
        if (s + 1 < nsteps) {
            uint32_t bw = ((uint32_t)((s + 1) & 1)) * QSS;
            long ka = (long)(s + 1) * 8;
            cpa16(sb + (bw + adw) * 4, QHr + ka);
            cpa16(sb + (bw + 1536 + adw) * 4, QLr + ka);
            cpa16(sb + (bw + 3072 + adw) * 4, KHr + ka);
            cpa16(sb + (bw + 4608 + adw) * 4, KLr + ka);
            cp_commit();
        }
        compute_at(dsw + (s & 1) * QSS, acc, m0w, n0w, g, t);
    }

    int ma, na;
    #pragma unroll
    for (ma = 0; ma < 4; ma++) {
        long r = row0 + m0w + ma * 16 + g;
        #pragma unroll
        for (na = 0; na < 4; na++) {
            long c = col0 + n0w + na * 8 + 2 * t;
            C[r * S_DIM + c]           = acc[ma][na][0] * scale;
            C[r * S_DIM + c + 1]       = acc[ma][na][1] * scale;
            C[(r + 8) * S_DIM + c]     = acc[ma][na][2] * scale;
            C[(r + 8) * S_DIM + c + 1] = acc[ma][na][3] * scale;
        }
    }
}

// ---------------- partial[z] = sum_{h in group z} attn[h] @ V[h] ------------
__global__ void __launch_bounds__(256) bf_attn_av(
    const uint32_t *Athi, const uint32_t *Atlo,
    const uint32_t *Vhi, const uint32_t *Vlo,
    float *Pg)
{
    extern __shared__ uint32_t dsw[];
    uint32_t sb = s2u(dsw);

    int tid = threadIdx.x;
    int lane = tid & 31;
    int warp = tid >> 5;
    int g = lane >> 2;
    int t = lane & 3;
    int m0w = (warp >> 2) * 64;
    int n0w = (warp & 3) * 32;
    long row0 = (long)blockIdx.y * 128;
    long col0 = (long)blockIdx.x * 128;

    int arow = tid >> 1;
    int ahalf = (tid & 1) * 4;
    int bk2 = tid >> 5;
    int bnc = (tid & 31) * 4;

    int nk = ((int)blockIdx.y + 1) * 8;
    int total = 4 * nk;
    int h0 = (int)blockIdx.z * 4;
    long S2 = S_DIM / 2;

    uint32_t adw = (uint32_t)(arow * 12 + ahalf);
    uint32_t bdw = (uint32_t)(bk2 * 136 + bnc);

    float acc[4][4][4];
    int i0, i1, i2;
    #pragma unroll
    for (i0 = 0; i0 < 4; i0++)
        #pragma unroll
        for (i1 = 0; i1 < 4; i1++)
            #pragma unroll
            for (i2 = 0; i2 < 4; i2++)
                acc[i0][i1][i2] = 0.0f;

    int s;
    {
        long ab = ((long)h0 * S_DIM + row0 + arow) * S2 + ahalf;
        long bb = ((long)h0 * S2 + bk2) * E_DIM + col0 + bnc;
        cpa16(sb + adw * 4, Athi + ab);
        cpa16(sb + (1536 + adw) * 4, Atlo + ab);
        cpa16(sb + (3072 + bdw) * 4, Vhi + bb);
        cpa16(sb + (4160 + bdw) * 4, Vlo + bb);
        cp_commit();
    }
    for (s = 0; s < total; s++) {
        cp_wait0();
        __syncthreads();
        if (s + 1 < total) {
            int j = s + 1;
            int hh = h0 + j / nk;
            int kk = j % nk;
            uint32_t bw = ((uint32_t)(j & 1)) * WSS;
            long ab = ((long)hh * S_DIM + row0 + arow) * S2
                    + (long)kk * 8 + ahalf;
            long bb = ((long)hh * S2 + (long)kk * 8 + bk2) * E_DIM
                    + col0 + bnc;
            cpa16(sb + (bw + adw) * 4, Athi + ab);
            cpa16(sb + (bw + 1536 + adw) * 4, Atlo + ab);
            cpa16(sb + (bw + 3072 + bdw) * 4, Vhi + bb);
            cpa16(sb + (bw + 4160 + bdw) * 4, Vlo + bb);
            cp_commit();
        }
        compute_bt(dsw + (s & 1) * WSS, acc, m0w, n0w, g, t);
    }

    float *P = Pg + (long)blockIdx.z * S_DIM * E_DIM;
    int ma, na;
    #pragma unroll
    for (ma = 0; ma < 4; ma++) {
        long r = row0 + m0w + ma * 16 + g;
        #pragma unroll
        for (na = 0; na < 4; na++) {
            long c = col0 + n0w + na * 8 + 2 * t;
            P[r * E_DIM + c]           = acc[ma][na][0];
            P[r * E_DIM + c + 1]       = acc[ma][na][1];
            P[(r + 8) * E_DIM + c]     = acc[ma][na][2];
            P[(r + 8) * E_DIM + c + 1] = acc[ma][na][3];
        }
    }
}

// py = x + p0 + p1 + p2 + p3 (fixed order, deterministic)
__global__ void __launch_bounds__(256) reduce4(
    const float *x, const float *p, float *py)
{
    long stride = (long)gridDim.x * 256;
    long i;
    for (i = (long)blockIdx.x * 256 + threadIdx.x; i < NTOT; i += stride) {
        float v = x[i];
        v += p[i];
        v += p[NTOT + i];
        v += p[2 * NTOT + i];
        v += p[3 * NTOT + i];
        py[i] = v;
    }
}

// ---------------- causal row softmax -> split attn (hi/lo pairs) ------------
__global__ void __launch_bounds__(256) softmax_causal(
    const float *sc, uint32_t *athi, uint32_t *atlo)
{
    __shared__ float buf[S_DIM];
    __shared__ float red[256];

    int s = blockIdx.x;
    int h = blockIdx.y;
    const float *row = sc + ((long)h * S_DIM + s) * (long)S_DIM;
    long out2 = ((long)h * S_DIM + s) * (long)(S_DIM / 2);
    int tid = threadIdx.x;
    int len = s + 1;
    int i;
    int st;

    float lmax = -INFINITY;
    for (i = tid; i < len; i += 256) {
        float v = row[i];
        buf[i] = v;
        lmax = fmaxf(lmax, v);
    }
    red[tid] = lmax;
    __syncthreads();
    for (st = 128; st > 0; st >>= 1) {
        if (tid < st) red[tid] = fmaxf(red[tid], red[tid + st]);
        __syncthreads();
    }
    float m = red[0];
    __syncthreads();

    float lsum = 0.0f;
    for (i = tid; i < len; i += 256) {
        float e = __expf(buf[i] - m);
        buf[i] = e;
        lsum += e;
    }
    red[tid] = lsum;
    __syncthreads();
    for (st = 128; st > 0; st >>= 1) {
        if (tid < st) red[tid] = red[tid] + red[tid + st];
        __syncthreads();
    }
    float inv = 1.0f / red[0];
    for (i = tid; i < S_DIM / 2; i += 256) {
        int i0 = 2 * i;
        int i1 = 2 * i + 1;
        float a = (i0 < len) ? buf[i0] * inv : 0.0f;
        float b = (i1 < len) ? buf[i1] * inv : 0.0f;
        uint32_t hh, ll;
        split_pair(a, b, hh, ll);
        athi[out2 + i] = hh;
        atlo[out2 + i] = ll;
    }
}

// ---------------- global LayerNorm ------------------------------------------
__global__ void __launch_bounds__(256) ln_reduce(const float *y, double *part)
{
    __shared__ double sd[256];
    __shared__ double sq[256];

    double s = 0.0;
    double ss = 0.0;
    long stride = (long)gridDim.x * 256;
    long i;
    int st;
    for (i = (long)blockIdx.x * 256 + threadIdx.x; i < NTOT; i += stride) {
        double v = (double)y[i];
        s += v;
        ss += v * v;
    }
    sd[threadIdx.x] = s;
    sq[threadIdx.x] = ss;
    __syncthreads();
    for (st = 128; st > 0; st >>= 1) {
        if (threadIdx.x < st) {
            sd[threadIdx.x] = sd[threadIdx.x] + sd[threadIdx.x + st];
            sq[threadIdx.x] = sq[threadIdx.x] + sq[threadIdx.x + st];
        }
        __syncthreads();
    }
    if (threadIdx.x == 0) {
        part[blockIdx.x] = sd[0];
        part[1024 + blockIdx.x] = sq[0];
    }
}

__global__ void __launch_bounds__(256) ln_finalize(const double *part, float *stats)
{
    __shared__ double sd[256];
    __shared__ double sq[256];

    double s = 0.0;
    double ss = 0.0;
    int i;
    int st;
    for (i = threadIdx.x; i < 1024; i += 256) {
        s += part[i];
        ss += part[1024 + i];
    }
    sd[threadIdx.x] = s;
    sq[threadIdx.x] = ss;
    __syncthreads();
    for (st = 128; st > 0; st >>= 1) {
        if (threadIdx.x < st) {
            sd[threadIdx.x] = sd[threadIdx.x] + sd[threadIdx.x + st];
            sq[threadIdx.x] = sq[threadIdx.x] + sq[threadIdx.x + st];
        }
        __syncthreads();
    }
    if (threadIdx.x == 0) {
        double mean = sd[0] / (double)NTOT;
        double var = sq[0] / (double)NTOT - mean * mean;
        stats[0] = (float)mean;
        stats[1] = (float)(1.0 / sqrt(var + (double)EPS));
    }
}

__global__ void __launch_bounds__(256) ln_apply(
    const float *y, const float *g, const float *b,
    const float *st, float *of32, uint32_t *ohi, uint32_t *olo)
{
    float m = st[0];
    float is = st[1];
    long stride = (long)gridDim.x * 256;
    long i;
    for (i = (long)blockIdx.x * 256 + threadIdx.x; i < NTOT / 2; i += stride) {
        long i0 = 2 * i;
        long i1 = 2 * i + 1;
        float v0 = (y[i0] - m) * is * g[i0] + b[i0];
        float v1 = (y[i1] - m) * is * g[i1] + b[i1];
        if (of32 != 0) {
            of32[i0] = v0;
            of32[i1] = v1;
        }
        if (ohi != 0) {
            uint32_t hh, ll;
            split_pair(v0, v1, hh, ll);
            ohi[i] = hh;
            olo[i] = ll;
        }
    }
}

// ---------------- host orchestration ----------------------------------------
extern "C" void kernel_launch(void* const* d_in, const int* in_sizes, int n_in,
                              void* d_out, int out_size)
{
    const float *x  = (const float *)d_in[0];
    const float *Wq = (const float *)d_in[1];
    const float *bq = (const float *)d_in[2];
    const float *Wk = (const float *)d_in[3];
    const float *bk = (const float *)d_in[4];
    const float *Wv = (const float *)d_in[5];
    const float *bv = (const float *)d_in[6];
    const float *lg = (const float *)d_in[7];
    const float *lb = (const float *)d_in[8];
    const float *W1 = (const float *)d_in[9];
    const float *b1 = (const float *)d_in[10];
    const float *W2 = (const float *)d_in[11];
    const float *b2 = (const float *)d_in[12];
    float *out = (float *)d_out;

    void *pv_[32];
    cudaGetSymbolAddress(&pv_[0],  g_sc);
    cudaGetSymbolAddress(&pv_[1],  g_y);
    cudaGetSymbolAddress(&pv_[2],  g_h);
    cudaGetSymbolAddress(&pv_[3],  g_pt);
    cudaGetSymbolAddress(&pv_[4],  g_part);
    cudaGetSymbolAddress(&pv_[5],  g_stats);
    cudaGetSymbolAddress(&pv_[6],  g_xhi);
    cudaGetSymbolAddress(&pv_[7],  g_xlo);
    cudaGetSymbolAddress(&pv_[8],  g_wqhi);
    cudaGetSymbolAddress(&pv_[9],  g_wqlo);
    cudaGetSymbolAddress(&pv_[10], g_wkhi);
    cudaGetSymbolAddress(&pv_[11], g_wklo);
    cudaGetSymbolAddress(&pv_[12], g_wvhi);
    cudaGetSymbolAddress(&pv_[13], g_wvlo);
    cudaGetSymbolAddress(&pv_[14], g_w1hi);
    cudaGetSymbolAddress(&pv_[15], g_w1lo);
    cudaGetSymbolAddress(&pv_[16], g_w2hi);
    cudaGetSymbolAddress(&pv_[17], g_w2lo);
    cudaGetSymbolAddress(&pv_[18], g_qhi);
    cudaGetSymbolAddress(&pv_[19], g_qlo);
    cudaGetSymbolAddress(&pv_[20], g_khi);
    cudaGetSymbolAddress(&pv_[21], g_klo);
    cudaGetSymbolAddress(&pv_[22], g_vhi);
    cudaGetSymbolAddress(&pv_[23], g_vlo);
    cudaGetSymbolAddress(&pv_[24], g_athi);
    cudaGetSymbolAddress(&pv_[25], g_atlo);
    cudaGetSymbolAddress(&pv_[26], g_hhi);
    cudaGetSymbolAddress(&pv_[27], g_hlo);
    cudaGetSymbolAddress(&pv_[28], g_ffhi);
    cudaGetSymbolAddress(&pv_[29], g_fflo);

    float *psc    = (float *)pv_[0];
    float *py     = (float *)pv_[1];
    float *ph     = (float *)pv_[2];
    float *ppt    = (float *)pv_[3];
    double *ppart = (double *)pv_[4];
    float *pstats = (float *)pv_[5];
    uint32_t *xhi = (uint32_t *)pv_[6],  *xlo = (uint32_t *)pv_[7];
    uint32_t *wqh = (uint32_t *)pv_[8],  *wql = (uint32_t *)pv_[9];
    uint32_t *wkh = (uint32_t *)pv_[10], *wkl = (uint32_t *)pv_[11];
    uint32_t *wvh = (uint32_t *)pv_[12], *wvl = (uint32_t *)pv_[13];
    uint32_t *w1h = (uint32_t *)pv_[14], *w1l = (uint32_t *)pv_[15];
    uint32_t *w2h = (uint32_t *)pv_[16], *w2l = (uint32_t *)pv_[17];
    uint32_t *qh  = (uint32_t *)pv_[18], *ql  = (uint32_t *)pv_[19];
    uint32_t *kh  = (uint32_t *)pv_[20], *kl  = (uint32_t *)pv_[21];
    uint32_t *vh  = (uint32_t *)pv_[22], *vl  = (uint32_t *)pv_[23];
    uint32_t *ath = (uint32_t *)pv_[24], *atl = (uint32_t *)pv_[25];
    uint32_t *hh  = (uint32_t *)pv_[26], *hl  = (uint32_t *)pv_[27];
    uint32_t *ffh = (uint32_t *)pv_[28], *ffl = (uint32_t *)pv_[29];

    cudaFuncSetAttribute(bf_gemm,
                         cudaFuncAttributeMaxDynamicSharedMemorySize, SM_BT);
    cudaFuncSetAttribute(bf_qkt,
                         cudaFuncAttributeMaxDynamicSharedMemorySize, SM_QK);
    cudaFuncSetAttribute(bf_attn_av,
                         cudaFuncAttributeMaxDynamicSharedMemorySize, SM_BT);

    dim3 blk(256, 1, 1);
    float scale = 1.0f / sqrtf((float)KD_DIM);

    // -------- operand splits (W2 split deferred) --------
    split_rowpair<<<2048, blk>>>(x, xhi, xlo, NTOT / 2);
    split_colpair3d<<<dim3(KD_DIM / 256 + 1, E_DIM / 2, H_DIM), blk>>>(
        Wq, wqh, wql, E_DIM, KD_DIM);
    split_colpair3d<<<dim3(KD_DIM / 256 + 1, E_DIM / 2, H_DIM), blk>>>(
        Wk, wkh, wkl, E_DIM, KD_DIM);
    split_colpair3d<<<dim3(E_DIM / 256, E_DIM / 2, H_DIM), blk>>>(
        Wv, wvh, wvl, E_DIM, E_DIM);
    split_colpair3d<<<dim3(FF_DIM / 256, E_DIM / 2, 1), blk>>>(
        W1, w1h, w1l, E_DIM, FF_DIM);

    // -------- Q/K projections (A-split outputs) --------
    {
        dim3 gq(1, S_DIM / 128, H_DIM);
        bf_gemm<<<gq, blk, SM_BT>>>(xhi, xlo, wqh, wql, bq,
            (const float *)0, (float *)0, qh, ql, 1, E_DIM, KD_DIM,
            0L, (long)(E_DIM / 2) * KD_DIM, (long)KD_DIM,
            0L, (long)S_DIM * (KD_DIM / 2), 0);
        bf_gemm<<<gq, blk, SM_BT>>>(xhi, xlo, wkh, wkl, bk,
            (const float *)0, (float *)0, kh, kl, 1, E_DIM, KD_DIM,
            0L, (long)(E_DIM / 2) * KD_DIM, (long)KD_DIM,
            0L, (long)S_DIM * (KD_DIM / 2), 0);
    }
    // -------- V projection: fused B-type split output --------
    {
        dim3 gv(E_DIM / 128, S_DIM / 128, H_DIM);
        bf_gemm<<<gv, blk, SM_BT>>>(xhi, xlo, wvh, wvl, bv,
            (const float *)0, (float *)0, vh, vl, 2, E_DIM, E_DIM,
            0L, (long)(E_DIM / 2) * E_DIM, (long)E_DIM,
            0L, (long)(S_DIM / 2) * E_DIM, 0);
    }

    // -------- scores + causal softmax (fused attn split) --------
    {
        dim3 gs(S_DIM / 128, S_DIM / 128, H_DIM);
        bf_qkt<<<gs, blk, SM_QK>>>(qh, ql, kh, kl, psc, scale);
    }
    {
        dim3 gsm(S_DIM, H_DIM, 1);
        softmax_causal<<<gsm, blk>>>(psc, ath, atl);
    }

    // -------- attn @ V: 4 balanced head-groups + deterministic reduce -------
    {
        dim3 ga(E_DIM / 128, S_DIM / 128, 4);
        bf_attn_av<<<ga, blk, SM_BT>>>(ath, atl, vh, vl, ppt);
        reduce4<<<2048, blk>>>(x, ppt, py);
    }

    // -------- LN1 --------
    ln_reduce<<<1024, blk>>>(py, ppart);
    ln_finalize<<<1, blk>>>(ppart, pstats);
    ln_apply<<<2048, blk>>>(py, lg, lb, pstats, ph, hh, hl);

    // -------- deferred W2 split + FFN --------
    split_colpair3d<<<dim3(E_DIM / 256, FF_DIM / 2, 1), blk>>>(
        W2, w2h, w2l, FF_DIM, E_DIM);
    {
        dim3 g1(FF_DIM / 128, S_DIM / 128, 1);
        bf_gemm<<<g1, blk, SM_BT>>>(hh, hl, w1h, w1l, b1,
            (const float *)0, (float *)0, ffh, ffl, 1, E_DIM, FF_DIM,
            0L, 0L, 0L, 0L, 0L, 1);
        dim3 g2(E_DIM / 128, S_DIM / 128, 1);
        bf_gemm<<<g2, blk, SM_BT>>>(ffh, ffl, w2h, w2l, b2, ph,
            py, (uint32_t *)0, (uint32_t *)0, 0, FF_DIM, E_DIM,
            0L, 0L, 0L, (long)S_DIM * E_DIM, 0L, 0);
    }

    // -------- LN2 -> output --------
    ln_reduce<<<1024, blk>>>(py, ppart);
    ln_finalize<<<1, blk>>>(ppart, pstats);
    ln_apply<<<2048, blk>>>(py, lg, lb, pstats, out, (uint32_t *)0,
                            (uint32_t *)0);
}